// round 12
// baseline (speedup 1.0000x reference)
#include <cuda_runtime.h>
#include <cuda_bf16.h>
#include <cstdint>
#include <cstddef>

// ---------------- problem constants ----------------
#define DD   768
#define MTOK 16
#define SS   1024
#define BB   16
#define TT   (SS + MTOK)   // 1040
#define TP   1152          // padded kv len (array stride)
#define KPV  1088          // K extent for P*Vt GEMM (17 x 64)
#define NQ   (BB * SS)     // 16384
#define NKV  (BB * TT)     // 16640
#define SCALE 0.036084391824351615f

// ---------------- scratch (device globals) ----------------
__device__ __align__(256) __nv_bfloat16 g_kvhi[(size_t)NKV * DD];
__device__ __align__(256) __nv_bfloat16 g_kvlo[(size_t)NKV * DD];
__device__ __align__(256) __nv_bfloat16 g_qhi [(size_t)NQ  * DD];
__device__ __align__(256) __nv_bfloat16 g_qlo [(size_t)NQ  * DD];
__device__ __align__(256) __nv_bfloat16 g_khi [(size_t)NKV * DD];
__device__ __align__(256) __nv_bfloat16 g_klo [(size_t)NKV * DD];
__device__ __align__(256) __nv_bfloat16 g_vthi[(size_t)BB * DD * TP];
__device__ __align__(256) __nv_bfloat16 g_vtlo[(size_t)BB * DD * TP];
__device__ __align__(256) float         g_sc  [(size_t)BB * SS * TP];
__device__ __align__(256) __nv_bfloat16 g_phi [(size_t)BB * SS * TP];
__device__ __align__(256) __nv_bfloat16 g_plo [(size_t)BB * SS * TP];
__device__ __align__(256) __nv_bfloat16 g_hhi [(size_t)NQ  * DD];
__device__ __align__(256) __nv_bfloat16 g_hlo [(size_t)NQ  * DD];
__device__ __align__(256) __nv_bfloat16 g_whi [4][(size_t)DD * DD];
__device__ __align__(256) __nv_bfloat16 g_wlo [4][(size_t)DD * DD];

// ---------------- helpers ----------------
__device__ __forceinline__ void bsplit(float f, __nv_bfloat16& h, __nv_bfloat16& l) {
    h = __float2bfloat16(f);
    l = __float2bfloat16(f - __bfloat162float(h));
}
__device__ __forceinline__ uint32_t smem_u32(const void* p) {
    uint32_t a;
    asm("{ .reg .u64 t; cvta.to.shared.u64 t, %1; cvt.u32.u64 %0, t; }" : "=r"(a) : "l"(p));
    return a;
}
__device__ __forceinline__ void cp16(uint32_t dst, const void* src) {
    asm volatile("cp.async.cg.shared.global [%0], [%1], 16;" :: "r"(dst), "l"(src));
}
__device__ __forceinline__ void cp_commit() {
    asm volatile("cp.async.commit_group;" ::: "memory");
}
template <int N>
__device__ __forceinline__ void cp_wait() {
    asm volatile("cp.async.wait_group %0;" :: "n"(N) : "memory");
}
__device__ __forceinline__ void ldm4(uint32_t* r, uint32_t addr) {
    asm volatile("ldmatrix.sync.aligned.m8n8.x4.shared.b16 {%0,%1,%2,%3},[%4];"
                 : "=r"(r[0]), "=r"(r[1]), "=r"(r[2]), "=r"(r[3]) : "r"(addr));
}
__device__ __forceinline__ void mma16816(float* c, const uint32_t* a, const uint32_t* b) {
    asm volatile("mma.sync.aligned.m16n8k16.row.col.f32.bf16.bf16.f32 "
                 "{%0,%1,%2,%3},{%4,%5,%6,%7},{%8,%9},{%0,%1,%2,%3};"
                 : "+f"(c[0]), "+f"(c[1]), "+f"(c[2]), "+f"(c[3])
                 : "r"(a[0]), "r"(a[1]), "r"(a[2]), "r"(a[3]), "r"(b[0]), "r"(b[1]));
}

// ---------------- elementwise prep ----------------
__global__ void build_kv(const float4* __restrict__ x, const float4* __restrict__ mem) {
    const int n4 = NKV * (DD / 4);
    int i = blockIdx.x * 256 + threadIdx.x;
    if (i >= n4) return;
    int d4  = i % (DD / 4);
    int row = i / (DD / 4);
    int b = row / TT, t = row % TT;
    float4 v = (t < SS) ? x[(size_t)(b * SS + t) * (DD / 4) + d4]
                        : mem[(size_t)(t - SS) * (DD / 4) + d4];
    union { __nv_bfloat16 bb[4]; uint2 u; } H, L;
    bsplit(v.x, H.bb[0], L.bb[0]);
    bsplit(v.y, H.bb[1], L.bb[1]);
    bsplit(v.z, H.bb[2], L.bb[2]);
    bsplit(v.w, H.bb[3], L.bb[3]);
    ((uint2*)g_kvhi)[i] = H.u;
    ((uint2*)g_kvlo)[i] = L.u;
}

__global__ void split_all(const float4* __restrict__ w0, const float4* __restrict__ w1,
                          const float4* __restrict__ w2, const float4* __restrict__ w3) {
    const int w4 = DD * DD / 4;
    int i = blockIdx.x * 256 + threadIdx.x;
    if (i >= 4 * w4) return;
    int wsel = i / w4;
    int j    = i % w4;
    const float4* src = (wsel == 0) ? w0 : (wsel == 1) ? w1 : (wsel == 2) ? w2 : w3;
    float4 v = src[j];
    union { __nv_bfloat16 bb[4]; uint2 u; } H, L;
    bsplit(v.x, H.bb[0], L.bb[0]);
    bsplit(v.y, H.bb[1], L.bb[1]);
    bsplit(v.z, H.bb[2], L.bb[2]);
    bsplit(v.w, H.bb[3], L.bb[3]);
    ((uint2*)g_whi[wsel])[j] = H.u;
    ((uint2*)g_wlo[wsel])[j] = L.u;
}

// ---------------- HMMA split-bf16 GEMM, block 256x128, BK=64, 512 threads ----------------
// 16 warps (8x2), warp tile 32x64 (the R9-validated per-warp body).
// Stage: Ahi(32K)|Alo(32K)|Bhi(16K)|Blo(16K) = 96KB; 2-stage, ONE barrier per chunk.

#define AMATB 32768                // A per level: 256 rows x 128B
#define BMATB 16384                // B per level: 128 rows x 128B
#define STAGE (2 * AMATB + 2 * BMATB)   // 98304
#define GSMEM (2 * STAGE)               // 196608

__global__ void __launch_bounds__(512, 1)
gemm3(const __nv_bfloat16* __restrict__ Ahi, const __nv_bfloat16* __restrict__ Alo,
      long long sA, int ldA, int mrealA,
      const __nv_bfloat16* __restrict__ Bhi, const __nv_bfloat16* __restrict__ Blo,
      long long sB, int ldB, int nrealB,
      int K, float alpha,
      const float* __restrict__ bias, int bias_mode,   // 0 none, 1 over N, 2 over M
      const float* __restrict__ mask, int mask_ld, int mask_n,
      float* __restrict__ Cf, __nv_bfloat16* __restrict__ Chi, __nv_bfloat16* __restrict__ Clo,
      long long sC, int ldC)
{
    extern __shared__ char smem[];
    const uint32_t sb = smem_u32(smem);
    const int tid  = threadIdx.x;
    const int lane = tid & 31;
    const int warp = tid >> 5;
    const int wm = warp >> 1;          // 0..7 (32-row slabs)
    const int wn = warp & 1;           // 0..1 (64-col slabs)

    const int m0 = blockIdx.y * 256, n0 = blockIdx.x * 128;
    const __nv_bfloat16* pAh = Ahi + (size_t)blockIdx.z * sA;
    const __nv_bfloat16* pAl = Alo + (size_t)blockIdx.z * sA;
    const __nv_bfloat16* pBh = Bhi + (size_t)blockIdx.z * sB;
    const __nv_bfloat16* pBl = Blo + (size_t)blockIdx.z * sB;

    // ---- cp.async mapping ----
    // A: 512 threads = 256 rows x 2 levels; each thread fills one full 128B row (8 cp16)
    const int arow = tid >> 1, alev = tid & 1;
    int garow = m0 + arow * 1;  // rows 0..255 handled, but arow only 0..255
    {
        int gr = m0 + arow;
        garow = (gr >= mrealA) ? (mrealA - 1) : gr;
    }
    const __nv_bfloat16* srcA = (alev ? pAl : pAh) + (size_t)garow * ldA;
    const uint32_t aBase = (uint32_t)(alev * AMATB) + (uint32_t)arow * 128u;
    const uint32_t arw7  = (uint32_t)(arow & 7);

    // B: 512 threads = 128 rows x 2 levels x 2 halves; each thread fills 64B (4 cp16)
    const int brow = tid >> 2, bsub = tid & 3;
    const int blev = bsub >> 1, bhalf = bsub & 1;
    int gbrow = n0 + brow; if (gbrow >= nrealB) gbrow = nrealB - 1;
    const __nv_bfloat16* srcB = (blev ? pBl : pBh) + (size_t)gbrow * ldB + bhalf * 32;
    const uint32_t bBase = (uint32_t)(2 * AMATB + blev * BMATB) + (uint32_t)brow * 128u;
    const uint32_t brw7  = (uint32_t)(brow & 7);
    const uint32_t bu0   = (uint32_t)(bhalf * 4);

    const int nchunk = K >> 6;

    auto prefetch = [&](int c, int stg) {
        const uint32_t so = sb + (uint32_t)stg * STAGE;
        const int k0 = c << 6;
        #pragma unroll
        for (int j = 0; j < 8; j++)
            cp16(so + aBase + (((uint32_t)j ^ arw7) * 16), srcA + k0 + j * 8);
        #pragma unroll
        for (int j = 0; j < 4; j++)
            cp16(so + bBase + (((bu0 + (uint32_t)j) ^ brw7) * 16), srcB + k0 + j * 8);
    };

    float acc[2][8][4];
    #pragma unroll
    for (int i = 0; i < 2; i++)
        #pragma unroll
        for (int j = 0; j < 8; j++)
            #pragma unroll
            for (int q = 0; q < 4; q++) acc[i][j][q] = 0.0f;

    const uint32_t band = (uint32_t)(lane & 7);
    const uint32_t a_hi = (uint32_t)(lane >> 4);        // 0/1
    uint32_t arowt[2];
    #pragma unroll
    for (int mt = 0; mt < 2; mt++)
        arowt[mt] = (uint32_t)(wm * 32 + mt * 16 + (lane & 15)) * 128u;
    const uint32_t b_off = (uint32_t)(((lane >> 4) & 1) * 8 + (lane & 7));
    const uint32_t b_hi  = (uint32_t)((lane >> 3) & 1);

    prefetch(0, 0); cp_commit();

    for (int c = 0; c < nchunk; c++) {
        cp_wait<0>();
        __syncthreads();
        if (c + 1 < nchunk) { prefetch(c + 1, (c + 1) & 1); cp_commit(); }

        const uint32_t Ab = sb + (uint32_t)(c & 1) * STAGE;
        const uint32_t Bb = Ab + 2 * AMATB;

        #pragma unroll
        for (int ks = 0; ks < 4; ks++) {
            uint32_t ah[2][4], al[2][4];
            const uint32_t ua = (uint32_t)(ks * 2) + a_hi;
            #pragma unroll
            for (int mt = 0; mt < 2; mt++) {
                ldm4(ah[mt], Ab + 0 * AMATB + arowt[mt] + (ua ^ band) * 16);
                ldm4(al[mt], Ab + 1 * AMATB + arowt[mt] + (ua ^ band) * 16);
            }
            const uint32_t ub = (uint32_t)(ks * 2) + b_hi;
            #pragma unroll
            for (int ntp = 0; ntp < 4; ntp++) {
                uint32_t bh[4], bl[4];
                const uint32_t brt = (uint32_t)(wn * 64 + ntp * 16 + b_off) * 128u;
                ldm4(bh, Bb + 0 * BMATB + brt + (ub ^ band) * 16);
                ldm4(bl, Bb + 1 * BMATB + brt + (ub ^ band) * 16);
                #pragma unroll
                for (int mt = 0; mt < 2; mt++) {
                    mma16816(acc[mt][ntp * 2    ], ah[mt], bh);
                    mma16816(acc[mt][ntp * 2 + 1], ah[mt], bh + 2);
                }
                #pragma unroll
                for (int mt = 0; mt < 2; mt++) {
                    mma16816(acc[mt][ntp * 2    ], ah[mt], bl);
                    mma16816(acc[mt][ntp * 2 + 1], ah[mt], bl + 2);
                }
                #pragma unroll
                for (int mt = 0; mt < 2; mt++) {
                    mma16816(acc[mt][ntp * 2    ], al[mt], bh);
                    mma16816(acc[mt][ntp * 2 + 1], al[mt], bh + 2);
                }
            }
        }
    }

    // ---- epilogue ----
    float* pC = Cf ? (Cf + (size_t)blockIdx.z * sC) : (float*)0;
    __nv_bfloat16* pCh = Chi ? (Chi + (size_t)blockIdx.z * sC) : (__nv_bfloat16*)0;
    __nv_bfloat16* pCl = Clo ? (Clo + (size_t)blockIdx.z * sC) : (__nv_bfloat16*)0;

    #pragma unroll
    for (int mt = 0; mt < 2; mt++) {
        const int row0 = m0 + wm * 32 + mt * 16 + (lane >> 2);
        #pragma unroll
        for (int nt = 0; nt < 8; nt++) {
            const int col = n0 + wn * 64 + nt * 8 + (lane & 3) * 2;
            #pragma unroll
            for (int half = 0; half < 2; half++) {
                const int row = row0 + half * 8;
                float v0 = acc[mt][nt][half * 2    ] * alpha;
                float v1 = acc[mt][nt][half * 2 + 1] * alpha;
                if (bias_mode == 1) {
                    float2 bv = *(const float2*)(bias + col);
                    v0 += bv.x; v1 += bv.y;
                } else if (bias_mode == 2) {
                    float bm = bias[row];
                    v0 += bm; v1 += bm;
                }
                if (mask && col < mask_n) {
                    float2 mv = *(const float2*)(mask + (size_t)row * mask_ld + col);
                    v0 += mv.x; v1 += mv.y;
                }
                if (pC) {
                    float2 ov; ov.x = v0; ov.y = v1;
                    *(float2*)(pC + (size_t)row * ldC + col) = ov;
                } else {
                    __nv_bfloat16 h0, l0, h1, l1;
                    bsplit(v0, h0, l0);
                    bsplit(v1, h1, l1);
                    union { __nv_bfloat16 bb[2]; uint32_t u; } H, L;
                    H.bb[0] = h0; H.bb[1] = h1;
                    L.bb[0] = l0; L.bb[1] = l1;
                    *(uint32_t*)(pCh + (size_t)row * ldC + col) = H.u;
                    *(uint32_t*)(pCl + (size_t)row * ldC + col) = L.u;
                }
            }
        }
    }
}

// ---------------- softmax ----------------
__device__ __forceinline__ float wmax(float v) {
    #pragma unroll
    for (int o = 16; o > 0; o >>= 1) v = fmaxf(v, __shfl_xor_sync(0xFFFFFFFFu, v, o));
    return v;
}
__device__ __forceinline__ float wsum(float v) {
    #pragma unroll
    for (int o = 16; o > 0; o >>= 1) v += __shfl_xor_sync(0xFFFFFFFFu, v, o);
    return v;
}

__global__ void __launch_bounds__(256)
softmax_split(const float* __restrict__ SC, __nv_bfloat16* __restrict__ Phi,
              __nv_bfloat16* __restrict__ Plo)
{
    const size_t base = (size_t)blockIdx.x * TP;
    const float* rrow = SC + base;
    const int tid = threadIdx.x, lane = tid & 31, warp = tid >> 5;
    __shared__ float red[8];

    float v[5];
    float mx = -1e30f;
    #pragma unroll
    for (int i = 0; i < 5; i++) {
        int t = tid + i * 256;
        if (t < TT) { float x = rrow[t]; v[i] = x; mx = fmaxf(mx, x); }
        else v[i] = -1e30f;
    }
    mx = wmax(mx);
    if (lane == 0) red[warp] = mx;
    __syncthreads();
    if (warp == 0) {
        float x = (lane < 8) ? red[lane] : -1e30f;
        x = wmax(x);
        if (lane == 0) red[0] = x;
    }
    __syncthreads();
    mx = red[0];
    __syncthreads();

    float sum = 0.0f;
    #pragma unroll
    for (int i = 0; i < 5; i++) {
        int t = tid + i * 256;
        if (t < TT) { float e = expf(v[i] - mx); v[i] = e; sum += e; }
    }
    sum = wsum(sum);
    if (lane == 0) red[warp] = sum;
    __syncthreads();
    if (warp == 0) {
        float x = (lane < 8) ? red[lane] : 0.0f;
        x = wsum(x);
        if (lane == 0) red[0] = x;
    }
    __syncthreads();
    const float inv = 1.0f / red[0];

    #pragma unroll
    for (int i = 0; i < 5; i++) {
        int t = tid + i * 256;
        if (t < TT) {
            float p = v[i] * inv;
            __nv_bfloat16 hh, ll;
            bsplit(p, hh, ll);
            Phi[base + t] = hh;
            Plo[base + t] = ll;
        } else if (t < TP) {
            Phi[base + t] = __float2bfloat16(0.0f);
            Plo[base + t] = __float2bfloat16(0.0f);
        }
    }
}

// ---------------- launch ----------------
extern "C" void kernel_launch(void* const* d_in, const int* in_sizes, int n_in,
                              void* d_out, int out_size)
{
    const float* x    = (const float*)d_in[0];
    const float* mask = (const float*)d_in[1];
    const float* mem  = (const float*)d_in[2];
    const float* wq   = (const float*)d_in[3];
    const float* bq   = (const float*)d_in[4];
    const float* wk   = (const float*)d_in[5];
    const float* bk   = (const float*)d_in[6];
    const float* wv   = (const float*)d_in[7];
    const float* bv   = (const float*)d_in[8];
    const float* wo   = (const float*)d_in[9];
    const float* bo   = (const float*)d_in[10];
    float* out = (float*)d_out;

    __nv_bfloat16 *kvhi, *kvlo, *qhi, *qlo, *khi, *klo, *vthi, *vtlo, *phi, *plo, *hhi, *hlo;
    __nv_bfloat16 (*whi)[(size_t)DD * DD];
    __nv_bfloat16 (*wlo)[(size_t)DD * DD];
    float* sc;
    cudaGetSymbolAddress((void**)&kvhi, g_kvhi);
    cudaGetSymbolAddress((void**)&kvlo, g_kvlo);
    cudaGetSymbolAddress((void**)&qhi,  g_qhi);
    cudaGetSymbolAddress((void**)&qlo,  g_qlo);
    cudaGetSymbolAddress((void**)&khi,  g_khi);
    cudaGetSymbolAddress((void**)&klo,  g_klo);
    cudaGetSymbolAddress((void**)&vthi, g_vthi);
    cudaGetSymbolAddress((void**)&vtlo, g_vtlo);
    cudaGetSymbolAddress((void**)&sc,   g_sc);
    cudaGetSymbolAddress((void**)&phi,  g_phi);
    cudaGetSymbolAddress((void**)&plo,  g_plo);
    cudaGetSymbolAddress((void**)&hhi,  g_hhi);
    cudaGetSymbolAddress((void**)&hlo,  g_hlo);
    cudaGetSymbolAddress((void**)&whi,  g_whi);
    cudaGetSymbolAddress((void**)&wlo,  g_wlo);

    cudaFuncSetAttribute(gemm3, cudaFuncAttributeMaxDynamicSharedMemorySize, GSMEM);

    // 0: concat + split kv input
    {
        int n4 = NKV * (DD / 4);
        build_kv<<<(n4 + 255) / 256, 256>>>((const float4*)x, (const float4*)mem);
    }
    // 1: split all weights
    {
        int tot = 4 * (DD * DD / 4);
        split_all<<<(tot + 255) / 256, 256>>>((const float4*)wq, (const float4*)wk,
                                              (const float4*)wv, (const float4*)wo);
    }

    // 2: Q = x * wq^T + bq  (batched; A rows skip memory tokens)
    gemm3<<<dim3(DD / 128, SS / 256, BB), 512, GSMEM>>>(
        kvhi, kvlo, (long long)TT * DD, DD, SS,
        whi[0], wlo[0], 0, DD, DD,
        DD, 1.0f, bq, 1, nullptr, 0, 0,
        nullptr, qhi, qlo, (long long)SS * DD, DD);

    // 3: K = kv * wk^T + bk
    gemm3<<<dim3(DD / 128, NKV / 256, 1), 512, GSMEM>>>(
        kvhi, kvlo, 0, DD, NKV,
        whi[1], wlo[1], 0, DD, DD,
        DD, 1.0f, bk, 1, nullptr, 0, 0,
        nullptr, khi, klo, 0, DD);

    // 4: Vt[b] = wv * kv[b]^T + bv(rows)   [768 x TP]
    gemm3<<<dim3(TP / 128, DD / 256, BB), 512, GSMEM>>>(
        whi[2], wlo[2], 0, DD, DD,
        kvhi, kvlo, (long long)TT * DD, DD, TT,
        DD, 1.0f, bv, 2, nullptr, 0, 0,
        nullptr, vthi, vtlo, (long long)DD * TP, TP);

    // 5: scores[b] = SCALE * Q[b] K[b]^T + mask -> fp32
    gemm3<<<dim3(TP / 128, SS / 256, BB), 512, GSMEM>>>(
        qhi, qlo, (long long)SS * DD, DD, SS,
        khi, klo, (long long)TT * DD, DD, TT,
        DD, SCALE, nullptr, 0, mask, TT, TT,
        sc, nullptr, nullptr, (long long)SS * TP, TP);

    // 6: softmax -> split P (pad cols zeroed)
    softmax_split<<<NQ, 256>>>(sc, phi, plo);

    // 7: H[b] = P[b] * Vt[b]^T   (K = 1088, pads are exact zeros)
    gemm3<<<dim3(DD / 128, SS / 256, BB), 512, GSMEM>>>(
        phi, plo, (long long)SS * TP, TP, SS,
        vthi, vtlo, (long long)DD * TP, TP, DD,
        KPV, 1.0f, nullptr, 0, nullptr, 0, 0,
        nullptr, hhi, hlo, (long long)SS * DD, DD);

    // 8: out = H * wo^T + bo -> fp32 d_out
    gemm3<<<dim3(DD / 128, NQ / 256, 1), 512, GSMEM>>>(
        hhi, hlo, 0, DD, NQ,
        whi[3], wlo[3], 0, DD, DD,
        DD, 1.0f, bo, 1, nullptr, 0, 0,
        out, nullptr, nullptr, 0, DD);
}

// round 13
// speedup vs baseline: 1.3131x; 1.3131x over previous
#include <cuda_runtime.h>
#include <cuda_bf16.h>
#include <cstdint>
#include <cstddef>

// ---------------- problem constants ----------------
#define DD   768
#define MTOK 16
#define SS   1024
#define BB   16
#define TT   (SS + MTOK)   // 1040
#define TP   1152          // padded kv len (array stride)
#define KPV  1088          // K extent for P*Vt GEMM (17 x 64)
#define NQ   (BB * SS)     // 16384
#define NKV  (BB * TT)     // 16640
#define SCALE 0.036084391824351615f

// ---------------- scratch (device globals) ----------------
__device__ __align__(256) __nv_bfloat16 g_kvhi[(size_t)NKV * DD];
__device__ __align__(256) __nv_bfloat16 g_kvlo[(size_t)NKV * DD];
__device__ __align__(256) __nv_bfloat16 g_qhi [(size_t)NQ  * DD];
__device__ __align__(256) __nv_bfloat16 g_qlo [(size_t)NQ  * DD];
__device__ __align__(256) __nv_bfloat16 g_khi [(size_t)NKV * DD];
__device__ __align__(256) __nv_bfloat16 g_klo [(size_t)NKV * DD];
__device__ __align__(256) __nv_bfloat16 g_vthi[(size_t)BB * DD * TP];
__device__ __align__(256) __nv_bfloat16 g_vtlo[(size_t)BB * DD * TP];
__device__ __align__(256) float         g_sc  [(size_t)BB * SS * TP];
__device__ __align__(256) __nv_bfloat16 g_phi [(size_t)BB * SS * TP];
__device__ __align__(256) __nv_bfloat16 g_plo [(size_t)BB * SS * TP];
__device__ __align__(256) __nv_bfloat16 g_hhi [(size_t)NQ  * DD];
__device__ __align__(256) __nv_bfloat16 g_hlo [(size_t)NQ  * DD];
__device__ __align__(256) __nv_bfloat16 g_whi [4][(size_t)DD * DD];
__device__ __align__(256) __nv_bfloat16 g_wlo [4][(size_t)DD * DD];

// ---------------- helpers ----------------
__device__ __forceinline__ void bsplit(float f, __nv_bfloat16& h, __nv_bfloat16& l) {
    h = __float2bfloat16(f);
    l = __float2bfloat16(f - __bfloat162float(h));
}
__device__ __forceinline__ uint32_t smem_u32(const void* p) {
    uint32_t a;
    asm("{ .reg .u64 t; cvta.to.shared.u64 t, %1; cvt.u32.u64 %0, t; }" : "=r"(a) : "l"(p));
    return a;
}
__device__ __forceinline__ void cp16(uint32_t dst, const void* src) {
    asm volatile("cp.async.cg.shared.global [%0], [%1], 16;" :: "r"(dst), "l"(src));
}
__device__ __forceinline__ void cp_commit() {
    asm volatile("cp.async.commit_group;" ::: "memory");
}
template <int N>
__device__ __forceinline__ void cp_wait() {
    asm volatile("cp.async.wait_group %0;" :: "n"(N) : "memory");
}
__device__ __forceinline__ void ldm4(uint32_t* r, uint32_t addr) {
    asm volatile("ldmatrix.sync.aligned.m8n8.x4.shared.b16 {%0,%1,%2,%3},[%4];"
                 : "=r"(r[0]), "=r"(r[1]), "=r"(r[2]), "=r"(r[3]) : "r"(addr));
}
__device__ __forceinline__ void mma16816(float* c, const uint32_t* a, const uint32_t* b) {
    asm volatile("mma.sync.aligned.m16n8k16.row.col.f32.bf16.bf16.f32 "
                 "{%0,%1,%2,%3},{%4,%5,%6,%7},{%8,%9},{%0,%1,%2,%3};"
                 : "+f"(c[0]), "+f"(c[1]), "+f"(c[2]), "+f"(c[3])
                 : "r"(a[0]), "r"(a[1]), "r"(a[2]), "r"(a[3]), "r"(b[0]), "r"(b[1]));
}

// ---------------- elementwise prep ----------------
__global__ void build_kv(const float4* __restrict__ x, const float4* __restrict__ mem) {
    const int n4 = NKV * (DD / 4);
    int i = blockIdx.x * 256 + threadIdx.x;
    if (i >= n4) return;
    int d4  = i % (DD / 4);
    int row = i / (DD / 4);
    int b = row / TT, t = row % TT;
    float4 v = (t < SS) ? x[(size_t)(b * SS + t) * (DD / 4) + d4]
                        : mem[(size_t)(t - SS) * (DD / 4) + d4];
    union { __nv_bfloat16 bb[4]; uint2 u; } H, L;
    bsplit(v.x, H.bb[0], L.bb[0]);
    bsplit(v.y, H.bb[1], L.bb[1]);
    bsplit(v.z, H.bb[2], L.bb[2]);
    bsplit(v.w, H.bb[3], L.bb[3]);
    ((uint2*)g_kvhi)[i] = H.u;
    ((uint2*)g_kvlo)[i] = L.u;
}

__global__ void split_all(const float4* __restrict__ w0, const float4* __restrict__ w1,
                          const float4* __restrict__ w2, const float4* __restrict__ w3) {
    const int w4 = DD * DD / 4;
    int i = blockIdx.x * 256 + threadIdx.x;
    if (i >= 4 * w4) return;
    int wsel = i / w4;
    int j    = i % w4;
    const float4* src = (wsel == 0) ? w0 : (wsel == 1) ? w1 : (wsel == 2) ? w2 : w3;
    float4 v = src[j];
    union { __nv_bfloat16 bb[4]; uint2 u; } H, L;
    bsplit(v.x, H.bb[0], L.bb[0]);
    bsplit(v.y, H.bb[1], L.bb[1]);
    bsplit(v.z, H.bb[2], L.bb[2]);
    bsplit(v.w, H.bb[3], L.bb[3]);
    ((uint2*)g_whi[wsel])[j] = H.u;
    ((uint2*)g_wlo[wsel])[j] = L.u;
}

// ---------------- HMMA split-bf16 GEMM, block 128x64, BK=64, 256 threads, 2 CTAs/SM ----
// 8 warps (4x2), warp tile 32x32 (the R11-validated body).
// Stage: Ahi(16K)|Alo(16K)|Bhi(8K)|Blo(8K) = 48KB; 2-stage = 96KB/CTA -> 2 CTAs/SM.
// Co-resident CTAs desynchronize barrier phases so the tensor pipe stays fed.

#define AMATB 16384                // A per level: 128 rows x 128B
#define BMATB 8192                 // B per level:  64 rows x 128B
#define STAGE (2 * AMATB + 2 * BMATB)   // 49152
#define GSMEM (2 * STAGE)               // 98304

__global__ void __launch_bounds__(256, 2)
gemm3(const __nv_bfloat16* __restrict__ Ahi, const __nv_bfloat16* __restrict__ Alo,
      long long sA, int ldA, int mrealA,
      const __nv_bfloat16* __restrict__ Bhi, const __nv_bfloat16* __restrict__ Blo,
      long long sB, int ldB, int nrealB,
      int K, float alpha,
      const float* __restrict__ bias, int bias_mode,   // 0 none, 1 over N, 2 over M
      const float* __restrict__ mask, int mask_ld, int mask_n,
      float* __restrict__ Cf, __nv_bfloat16* __restrict__ Chi, __nv_bfloat16* __restrict__ Clo,
      long long sC, int ldC)
{
    extern __shared__ char smem[];
    const uint32_t sb = smem_u32(smem);
    const int tid  = threadIdx.x;
    const int lane = tid & 31;
    const int warp = tid >> 5;
    const int wm = warp >> 1;          // 0..3 (32-row slabs)
    const int wn = warp & 1;           // 0..1 (32-col slabs)

    const int m0 = blockIdx.y * 128, n0 = blockIdx.x * 64;
    const __nv_bfloat16* pAh = Ahi + (size_t)blockIdx.z * sA;
    const __nv_bfloat16* pAl = Alo + (size_t)blockIdx.z * sA;
    const __nv_bfloat16* pBh = Bhi + (size_t)blockIdx.z * sB;
    const __nv_bfloat16* pBl = Blo + (size_t)blockIdx.z * sB;

    // ---- cp.async mapping ----
    // A: 256 threads = 128 rows x 2 levels; each thread fills one full 128B row (8 cp16)
    const int arow = tid >> 1, alev = tid & 1;
    int gar = m0 + arow; if (gar >= mrealA) gar = mrealA - 1;
    const __nv_bfloat16* srcA = (alev ? pAl : pAh) + (size_t)gar * ldA;
    const uint32_t aBase = (uint32_t)(alev * AMATB) + (uint32_t)arow * 128u;
    const uint32_t arw7  = (uint32_t)(arow & 7);

    // B: 256 threads = 64 rows x 2 levels x 2 halves; each thread fills 64B (4 cp16)
    const int brow = tid >> 2, bsub = tid & 3;
    const int blev = bsub >> 1, bhalf = bsub & 1;
    int gbr = n0 + brow; if (gbr >= nrealB) gbr = nrealB - 1;
    const __nv_bfloat16* srcB = (blev ? pBl : pBh) + (size_t)gbr * ldB + bhalf * 32;
    const uint32_t bBase = (uint32_t)(2 * AMATB + blev * BMATB) + (uint32_t)brow * 128u;
    const uint32_t brw7  = (uint32_t)(brow & 7);
    const uint32_t bu0   = (uint32_t)(bhalf * 4);

    const int nchunk = K >> 6;

    auto prefetch = [&](int c, int stg) {
        const uint32_t so = sb + (uint32_t)stg * STAGE;
        const int k0 = c << 6;
        #pragma unroll
        for (int j = 0; j < 8; j++)
            cp16(so + aBase + (((uint32_t)j ^ arw7) * 16), srcA + k0 + j * 8);
        #pragma unroll
        for (int j = 0; j < 4; j++)
            cp16(so + bBase + (((bu0 + (uint32_t)j) ^ brw7) * 16), srcB + k0 + j * 8);
    };

    float acc[2][4][4];
    #pragma unroll
    for (int i = 0; i < 2; i++)
        #pragma unroll
        for (int j = 0; j < 4; j++)
            #pragma unroll
            for (int p = 0; p < 4; p++) acc[i][j][p] = 0.0f;

    const uint32_t band = (uint32_t)(lane & 7);
    const uint32_t a_hi = (uint32_t)(lane >> 4);        // 0/1
    uint32_t arowt[2];
    #pragma unroll
    for (int mt = 0; mt < 2; mt++)
        arowt[mt] = (uint32_t)(wm * 32 + mt * 16 + (lane & 15)) * 128u;
    const uint32_t b_off = (uint32_t)(((lane >> 4) & 1) * 8 + (lane & 7));
    const uint32_t b_hi  = (uint32_t)((lane >> 3) & 1);

    prefetch(0, 0); cp_commit();

    for (int c = 0; c < nchunk; c++) {
        cp_wait<0>();
        __syncthreads();
        if (c + 1 < nchunk) { prefetch(c + 1, (c + 1) & 1); cp_commit(); }

        const uint32_t Ab = sb + (uint32_t)(c & 1) * STAGE;
        const uint32_t Bb = Ab + 2 * AMATB;

        #pragma unroll
        for (int ks = 0; ks < 4; ks++) {
            uint32_t ah[2][4], al[2][4];
            const uint32_t ua = (uint32_t)(ks * 2) + a_hi;
            #pragma unroll
            for (int mt = 0; mt < 2; mt++) {
                ldm4(ah[mt], Ab + 0 * AMATB + arowt[mt] + (ua ^ band) * 16);
                ldm4(al[mt], Ab + 1 * AMATB + arowt[mt] + (ua ^ band) * 16);
            }
            const uint32_t ub = (uint32_t)(ks * 2) + b_hi;
            #pragma unroll
            for (int ntp = 0; ntp < 2; ntp++) {
                uint32_t bh[4], bl[4];
                const uint32_t brt = (uint32_t)(wn * 32 + ntp * 16 + b_off) * 128u;
                ldm4(bh, Bb + 0 * BMATB + brt + (ub ^ band) * 16);
                ldm4(bl, Bb + 1 * BMATB + brt + (ub ^ band) * 16);
                #pragma unroll
                for (int mt = 0; mt < 2; mt++) {
                    mma16816(acc[mt][ntp * 2    ], ah[mt], bh);
                    mma16816(acc[mt][ntp * 2 + 1], ah[mt], bh + 2);
                }
                #pragma unroll
                for (int mt = 0; mt < 2; mt++) {
                    mma16816(acc[mt][ntp * 2    ], ah[mt], bl);
                    mma16816(acc[mt][ntp * 2 + 1], ah[mt], bl + 2);
                }
                #pragma unroll
                for (int mt = 0; mt < 2; mt++) {
                    mma16816(acc[mt][ntp * 2    ], al[mt], bh);
                    mma16816(acc[mt][ntp * 2 + 1], al[mt], bh + 2);
                }
            }
        }
    }

    // ---- epilogue ----
    float* pC = Cf ? (Cf + (size_t)blockIdx.z * sC) : (float*)0;
    __nv_bfloat16* pCh = Chi ? (Chi + (size_t)blockIdx.z * sC) : (__nv_bfloat16*)0;
    __nv_bfloat16* pCl = Clo ? (Clo + (size_t)blockIdx.z * sC) : (__nv_bfloat16*)0;

    #pragma unroll
    for (int mt = 0; mt < 2; mt++) {
        const int row0 = m0 + wm * 32 + mt * 16 + (lane >> 2);
        #pragma unroll
        for (int nt = 0; nt < 4; nt++) {
            const int col = n0 + wn * 32 + nt * 8 + (lane & 3) * 2;
            #pragma unroll
            for (int half = 0; half < 2; half++) {
                const int row = row0 + half * 8;
                float v0 = acc[mt][nt][half * 2    ] * alpha;
                float v1 = acc[mt][nt][half * 2 + 1] * alpha;
                if (bias_mode == 1) {
                    float2 bv = *(const float2*)(bias + col);
                    v0 += bv.x; v1 += bv.y;
                } else if (bias_mode == 2) {
                    float bm = bias[row];
                    v0 += bm; v1 += bm;
                }
                if (mask && col < mask_n) {
                    float2 mv = *(const float2*)(mask + (size_t)row * mask_ld + col);
                    v0 += mv.x; v1 += mv.y;
                }
                if (pC) {
                    float2 ov; ov.x = v0; ov.y = v1;
                    *(float2*)(pC + (size_t)row * ldC + col) = ov;
                } else {
                    __nv_bfloat16 h0, l0, h1, l1;
                    bsplit(v0, h0, l0);
                    bsplit(v1, h1, l1);
                    union { __nv_bfloat16 bb[2]; uint32_t u; } H, L;
                    H.bb[0] = h0; H.bb[1] = h1;
                    L.bb[0] = l0; L.bb[1] = l1;
                    *(uint32_t*)(pCh + (size_t)row * ldC + col) = H.u;
                    *(uint32_t*)(pCl + (size_t)row * ldC + col) = L.u;
                }
            }
        }
    }
}

// ---------------- softmax ----------------
__device__ __forceinline__ float wmax(float v) {
    #pragma unroll
    for (int o = 16; o > 0; o >>= 1) v = fmaxf(v, __shfl_xor_sync(0xFFFFFFFFu, v, o));
    return v;
}
__device__ __forceinline__ float wsum(float v) {
    #pragma unroll
    for (int o = 16; o > 0; o >>= 1) v += __shfl_xor_sync(0xFFFFFFFFu, v, o);
    return v;
}

__global__ void __launch_bounds__(256)
softmax_split(const float* __restrict__ SC, __nv_bfloat16* __restrict__ Phi,
              __nv_bfloat16* __restrict__ Plo)
{
    const size_t base = (size_t)blockIdx.x * TP;
    const float* rrow = SC + base;
    const int tid = threadIdx.x, lane = tid & 31, warp = tid >> 5;
    __shared__ float red[8];

    float v[5];
    float mx = -1e30f;
    #pragma unroll
    for (int i = 0; i < 5; i++) {
        int t = tid + i * 256;
        if (t < TT) { float x = rrow[t]; v[i] = x; mx = fmaxf(mx, x); }
        else v[i] = -1e30f;
    }
    mx = wmax(mx);
    if (lane == 0) red[warp] = mx;
    __syncthreads();
    if (warp == 0) {
        float x = (lane < 8) ? red[lane] : -1e30f;
        x = wmax(x);
        if (lane == 0) red[0] = x;
    }
    __syncthreads();
    mx = red[0];
    __syncthreads();

    float sum = 0.0f;
    #pragma unroll
    for (int i = 0; i < 5; i++) {
        int t = tid + i * 256;
        if (t < TT) { float e = expf(v[i] - mx); v[i] = e; sum += e; }
    }
    sum = wsum(sum);
    if (lane == 0) red[warp] = sum;
    __syncthreads();
    if (warp == 0) {
        float x = (lane < 8) ? red[lane] : 0.0f;
        x = wsum(x);
        if (lane == 0) red[0] = x;
    }
    __syncthreads();
    const float inv = 1.0f / red[0];

    #pragma unroll
    for (int i = 0; i < 5; i++) {
        int t = tid + i * 256;
        if (t < TT) {
            float p = v[i] * inv;
            __nv_bfloat16 hh, ll;
            bsplit(p, hh, ll);
            Phi[base + t] = hh;
            Plo[base + t] = ll;
        } else if (t < TP) {
            Phi[base + t] = __float2bfloat16(0.0f);
            Plo[base + t] = __float2bfloat16(0.0f);
        }
    }
}

// ---------------- launch ----------------
extern "C" void kernel_launch(void* const* d_in, const int* in_sizes, int n_in,
                              void* d_out, int out_size)
{
    const float* x    = (const float*)d_in[0];
    const float* mask = (const float*)d_in[1];
    const float* mem  = (const float*)d_in[2];
    const float* wq   = (const float*)d_in[3];
    const float* bq   = (const float*)d_in[4];
    const float* wk   = (const float*)d_in[5];
    const float* bk   = (const float*)d_in[6];
    const float* wv   = (const float*)d_in[7];
    const float* bv   = (const float*)d_in[8];
    const float* wo   = (const float*)d_in[9];
    const float* bo   = (const float*)d_in[10];
    float* out = (float*)d_out;

    __nv_bfloat16 *kvhi, *kvlo, *qhi, *qlo, *khi, *klo, *vthi, *vtlo, *phi, *plo, *hhi, *hlo;
    __nv_bfloat16 (*whi)[(size_t)DD * DD];
    __nv_bfloat16 (*wlo)[(size_t)DD * DD];
    float* sc;
    cudaGetSymbolAddress((void**)&kvhi, g_kvhi);
    cudaGetSymbolAddress((void**)&kvlo, g_kvlo);
    cudaGetSymbolAddress((void**)&qhi,  g_qhi);
    cudaGetSymbolAddress((void**)&qlo,  g_qlo);
    cudaGetSymbolAddress((void**)&khi,  g_khi);
    cudaGetSymbolAddress((void**)&klo,  g_klo);
    cudaGetSymbolAddress((void**)&vthi, g_vthi);
    cudaGetSymbolAddress((void**)&vtlo, g_vtlo);
    cudaGetSymbolAddress((void**)&sc,   g_sc);
    cudaGetSymbolAddress((void**)&phi,  g_phi);
    cudaGetSymbolAddress((void**)&plo,  g_plo);
    cudaGetSymbolAddress((void**)&hhi,  g_hhi);
    cudaGetSymbolAddress((void**)&hlo,  g_hlo);
    cudaGetSymbolAddress((void**)&whi,  g_whi);
    cudaGetSymbolAddress((void**)&wlo,  g_wlo);

    cudaFuncSetAttribute(gemm3, cudaFuncAttributeMaxDynamicSharedMemorySize, GSMEM);

    // 0: concat + split kv input
    {
        int n4 = NKV * (DD / 4);
        build_kv<<<(n4 + 255) / 256, 256>>>((const float4*)x, (const float4*)mem);
    }
    // 1: split all weights
    {
        int tot = 4 * (DD * DD / 4);
        split_all<<<(tot + 255) / 256, 256>>>((const float4*)wq, (const float4*)wk,
                                              (const float4*)wv, (const float4*)wo);
    }

    // 2: Q = x * wq^T + bq  (batched; A rows skip memory tokens)
    gemm3<<<dim3(DD / 64, SS / 128, BB), 256, GSMEM>>>(
        kvhi, kvlo, (long long)TT * DD, DD, SS,
        whi[0], wlo[0], 0, DD, DD,
        DD, 1.0f, bq, 1, nullptr, 0, 0,
        nullptr, qhi, qlo, (long long)SS * DD, DD);

    // 3: K = kv * wk^T + bk
    gemm3<<<dim3(DD / 64, NKV / 128, 1), 256, GSMEM>>>(
        kvhi, kvlo, 0, DD, NKV,
        whi[1], wlo[1], 0, DD, DD,
        DD, 1.0f, bk, 1, nullptr, 0, 0,
        nullptr, khi, klo, 0, DD);

    // 4: Vt[b] = wv * kv[b]^T + bv(rows)   [768 x TP]
    gemm3<<<dim3(TP / 64, DD / 128, BB), 256, GSMEM>>>(
        whi[2], wlo[2], 0, DD, DD,
        kvhi, kvlo, (long long)TT * DD, DD, TT,
        DD, 1.0f, bv, 2, nullptr, 0, 0,
        nullptr, vthi, vtlo, (long long)DD * TP, TP);

    // 5: scores[b] = SCALE * Q[b] K[b]^T + mask -> fp32
    gemm3<<<dim3(TP / 64, SS / 128, BB), 256, GSMEM>>>(
        qhi, qlo, (long long)SS * DD, DD, SS,
        khi, klo, (long long)TT * DD, DD, TT,
        DD, SCALE, nullptr, 0, mask, TT, TT,
        sc, nullptr, nullptr, (long long)SS * TP, TP);

    // 6: softmax -> split P (pad cols zeroed)
    softmax_split<<<NQ, 256>>>(sc, phi, plo);

    // 7: H[b] = P[b] * Vt[b]^T   (K = 1088, pads are exact zeros)
    gemm3<<<dim3(DD / 64, SS / 128, BB), 256, GSMEM>>>(
        phi, plo, (long long)SS * TP, TP, SS,
        vthi, vtlo, (long long)DD * TP, TP, DD,
        KPV, 1.0f, nullptr, 0, nullptr, 0, 0,
        nullptr, hhi, hlo, (long long)SS * DD, DD);

    // 8: out = H * wo^T + bo -> fp32 d_out
    gemm3<<<dim3(DD / 64, NQ / 128, 1), 256, GSMEM>>>(
        hhi, hlo, 0, DD, NQ,
        whi[3], wlo[3], 0, DD, DD,
        DD, 1.0f, bo, 1, nullptr, 0, 0,
        out, nullptr, nullptr, 0, DD);
}

// round 14
// speedup vs baseline: 1.8605x; 1.4169x over previous
#include <cuda_runtime.h>
#include <cuda_bf16.h>
#include <cstdint>
#include <cstddef>

// ---------------- problem constants ----------------
#define DD   768
#define MTOK 16
#define SS   1024
#define BB   16
#define TT   (SS + MTOK)   // 1040
#define TP   1152          // padded kv len (array stride)
#define KPV  1088          // K extent for P*Vt GEMM (17 x 64)
#define NQ   (BB * SS)     // 16384
#define NKV  (BB * TT)     // 16640
#define SCALE 0.036084391824351615f

// ---------------- scratch (device globals) ----------------
__device__ __align__(256) __nv_bfloat16 g_kvhi[(size_t)NKV * DD];
__device__ __align__(256) __nv_bfloat16 g_kvlo[(size_t)NKV * DD];
__device__ __align__(256) __nv_bfloat16 g_qhi [(size_t)NQ  * DD];
__device__ __align__(256) __nv_bfloat16 g_qlo [(size_t)NQ  * DD];
__device__ __align__(256) __nv_bfloat16 g_khi [(size_t)NKV * DD];
__device__ __align__(256) __nv_bfloat16 g_klo [(size_t)NKV * DD];
__device__ __align__(256) __nv_bfloat16 g_vthi[(size_t)BB * DD * TP];
__device__ __align__(256) __nv_bfloat16 g_vtlo[(size_t)BB * DD * TP];
__device__ __align__(256) float         g_sc  [(size_t)BB * SS * TP];
__device__ __align__(256) __nv_bfloat16 g_phi [(size_t)BB * SS * TP];
__device__ __align__(256) __nv_bfloat16 g_plo [(size_t)BB * SS * TP];
__device__ __align__(256) __nv_bfloat16 g_hhi [(size_t)NQ  * DD];
__device__ __align__(256) __nv_bfloat16 g_hlo [(size_t)NQ  * DD];
__device__ __align__(256) __nv_bfloat16 g_whi [4][(size_t)DD * DD];
__device__ __align__(256) __nv_bfloat16 g_wlo [4][(size_t)DD * DD];

// ---------------- helpers ----------------
__device__ __forceinline__ void bsplit(float f, __nv_bfloat16& h, __nv_bfloat16& l) {
    h = __float2bfloat16(f);
    l = __float2bfloat16(f - __bfloat162float(h));
}
__device__ __forceinline__ uint32_t smem_u32(const void* p) {
    uint32_t a;
    asm("{ .reg .u64 t; cvta.to.shared.u64 t, %1; cvt.u32.u64 %0, t; }" : "=r"(a) : "l"(p));
    return a;
}
__device__ __forceinline__ void cp16(uint32_t dst, const void* src) {
    asm volatile("cp.async.cg.shared.global [%0], [%1], 16;" :: "r"(dst), "l"(src));
}
__device__ __forceinline__ void cp_commit() {
    asm volatile("cp.async.commit_group;" ::: "memory");
}
template <int N>
__device__ __forceinline__ void cp_wait() {
    asm volatile("cp.async.wait_group %0;" :: "n"(N) : "memory");
}
__device__ __forceinline__ void ldm4(uint32_t* r, uint32_t addr) {
    asm volatile("ldmatrix.sync.aligned.m8n8.x4.shared.b16 {%0,%1,%2,%3},[%4];"
                 : "=r"(r[0]), "=r"(r[1]), "=r"(r[2]), "=r"(r[3]) : "r"(addr));
}
__device__ __forceinline__ void mma16816(float* c, const uint32_t* a, const uint32_t* b) {
    asm volatile("mma.sync.aligned.m16n8k16.row.col.f32.bf16.bf16.f32 "
                 "{%0,%1,%2,%3},{%4,%5,%6,%7},{%8,%9},{%0,%1,%2,%3};"
                 : "+f"(c[0]), "+f"(c[1]), "+f"(c[2]), "+f"(c[3])
                 : "r"(a[0]), "r"(a[1]), "r"(a[2]), "r"(a[3]), "r"(b[0]), "r"(b[1]));
}

// ---------------- elementwise prep ----------------
__global__ void build_kv(const float4* __restrict__ x, const float4* __restrict__ mem) {
    const int n4 = NKV * (DD / 4);
    int i = blockIdx.x * 256 + threadIdx.x;
    if (i >= n4) return;
    int d4  = i % (DD / 4);
    int row = i / (DD / 4);
    int b = row / TT, t = row % TT;
    float4 v = (t < SS) ? x[(size_t)(b * SS + t) * (DD / 4) + d4]
                        : mem[(size_t)(t - SS) * (DD / 4) + d4];
    union { __nv_bfloat16 bb[4]; uint2 u; } H, L;
    bsplit(v.x, H.bb[0], L.bb[0]);
    bsplit(v.y, H.bb[1], L.bb[1]);
    bsplit(v.z, H.bb[2], L.bb[2]);
    bsplit(v.w, H.bb[3], L.bb[3]);
    ((uint2*)g_kvhi)[i] = H.u;
    ((uint2*)g_kvlo)[i] = L.u;
}

__global__ void split_all(const float4* __restrict__ w0, const float4* __restrict__ w1,
                          const float4* __restrict__ w2, const float4* __restrict__ w3) {
    const int w4 = DD * DD / 4;
    int i = blockIdx.x * 256 + threadIdx.x;
    if (i >= 4 * w4) return;
    int wsel = i / w4;
    int j    = i % w4;
    const float4* src = (wsel == 0) ? w0 : (wsel == 1) ? w1 : (wsel == 2) ? w2 : w3;
    float4 v = src[j];
    union { __nv_bfloat16 bb[4]; uint2 u; } H, L;
    bsplit(v.x, H.bb[0], L.bb[0]);
    bsplit(v.y, H.bb[1], L.bb[1]);
    bsplit(v.z, H.bb[2], L.bb[2]);
    bsplit(v.w, H.bb[3], L.bb[3]);
    ((uint2*)g_whi[wsel])[j] = H.u;
    ((uint2*)g_wlo[wsel])[j] = L.u;
}

// ---------------- HMMA split-bf16 GEMM, BK=64, 512 threads, ks-staggered ----------------
// Block 128x128, 16 warps (4x4), warp tile 32x32 -> 4 warps/SMSP.
// Each SMSP's 4 warps start the ks loop at different offsets ((warp>>2)&3) so
// LDSM bursts and MMA streams interleave instead of convoying at the barrier.

#define MATB  16384                // one matrix tile: 128 x 128B
#define STAGE (4 * MATB)           // 65536
#define GSMEM (3 * STAGE)          // 196608

__global__ void __launch_bounds__(512, 1)
gemm3(const __nv_bfloat16* __restrict__ Ahi, const __nv_bfloat16* __restrict__ Alo,
      long long sA, int ldA, int mrealA,
      const __nv_bfloat16* __restrict__ Bhi, const __nv_bfloat16* __restrict__ Blo,
      long long sB, int ldB, int nrealB,
      int K, float alpha,
      const float* __restrict__ bias, int bias_mode,   // 0 none, 1 over N, 2 over M
      const float* __restrict__ mask, int mask_ld, int mask_n,
      float* __restrict__ Cf, __nv_bfloat16* __restrict__ Chi, __nv_bfloat16* __restrict__ Clo,
      long long sC, int ldC)
{
    extern __shared__ char smem[];
    const uint32_t sb = smem_u32(smem);
    const int tid  = threadIdx.x;
    const int lane = tid & 31;
    const int warp = tid >> 5;
    const int wm = warp >> 2;          // 0..3 (32-row slabs)
    const int wn = warp & 3;           // 0..3 (32-col slabs)
    const int kstag = (warp >> 2) & 3; // SMSP-mate stagger

    const int m0 = blockIdx.y * 128, n0 = blockIdx.x * 128;
    const __nv_bfloat16* pAh = Ahi + (size_t)blockIdx.z * sA;
    const __nv_bfloat16* pAl = Alo + (size_t)blockIdx.z * sA;
    const __nv_bfloat16* pBh = Bhi + (size_t)blockIdx.z * sB;
    const __nv_bfloat16* pBl = Blo + (size_t)blockIdx.z * sB;

    // ---- cp.async mapping: 4 threads per row, each covers 32B of the 128B row ----
    const int r = tid >> 2, q = tid & 3;
    int garow = m0 + r; if (garow >= mrealA) garow = mrealA - 1;
    int gbrow = n0 + r; if (gbrow >= nrealB) gbrow = nrealB - 1;
    const __nv_bfloat16* srcAh = pAh + (size_t)garow * ldA + q * 16;
    const __nv_bfloat16* srcAl = pAl + (size_t)garow * ldA + q * 16;
    const __nv_bfloat16* srcBh = pBh + (size_t)gbrow * ldB + q * 16;
    const __nv_bfloat16* srcBl = pBl + (size_t)gbrow * ldB + q * 16;
    uint32_t dstu[2];
    #pragma unroll
    for (int j = 0; j < 2; j++)
        dstu[j] = (uint32_t)r * 128u + (uint32_t)((((q << 1) + j) ^ (r & 7)) * 16);

    const int nchunk = K >> 6;

    auto prefetch = [&](int c, int stg) {
        const uint32_t so = sb + (uint32_t)stg * STAGE;
        const int k0 = c << 6;
        #pragma unroll
        for (int j = 0; j < 2; j++) cp16(so + 0 * MATB + dstu[j], srcAh + k0 + j * 8);
        #pragma unroll
        for (int j = 0; j < 2; j++) cp16(so + 1 * MATB + dstu[j], srcAl + k0 + j * 8);
        #pragma unroll
        for (int j = 0; j < 2; j++) cp16(so + 2 * MATB + dstu[j], srcBh + k0 + j * 8);
        #pragma unroll
        for (int j = 0; j < 2; j++) cp16(so + 3 * MATB + dstu[j], srcBl + k0 + j * 8);
    };

    float acc[2][4][4];
    #pragma unroll
    for (int i = 0; i < 2; i++)
        #pragma unroll
        for (int j = 0; j < 4; j++)
            #pragma unroll
            for (int p = 0; p < 4; p++) acc[i][j][p] = 0.0f;

    const uint32_t band = (uint32_t)(lane & 7);
    const uint32_t a_hi = (uint32_t)(lane >> 4);        // 0/1
    uint32_t arowt[2];
    #pragma unroll
    for (int mt = 0; mt < 2; mt++)
        arowt[mt] = (uint32_t)(wm * 32 + mt * 16 + (lane & 15)) * 128u;
    const uint32_t b_off = (uint32_t)(((lane >> 4) & 1) * 8 + (lane & 7));
    const uint32_t b_hi  = (uint32_t)((lane >> 3) & 1);

    prefetch(0, 0); cp_commit();
    if (nchunk > 1) prefetch(1, 1);
    cp_commit();

    for (int c = 0; c < nchunk; c++) {
        cp_wait<1>();
        __syncthreads();
        if (c + 2 < nchunk) prefetch(c + 2, (c + 2) % 3);
        cp_commit();

        const uint32_t Ab = sb + (uint32_t)(c % 3) * STAGE;
        const uint32_t Bb = Ab + 2 * MATB;

        #pragma unroll
        for (int kk = 0; kk < 4; kk++) {
            const int ks = (kk + kstag) & 3;    // SMSP-mates start at different ks
            uint32_t ah[2][4], al[2][4];
            const uint32_t ua = (uint32_t)(ks * 2) + a_hi;
            #pragma unroll
            for (int mt = 0; mt < 2; mt++) {
                ldm4(ah[mt], Ab + 0 * MATB + arowt[mt] + (ua ^ band) * 16);
                ldm4(al[mt], Ab + 1 * MATB + arowt[mt] + (ua ^ band) * 16);
            }
            const uint32_t ub = (uint32_t)(ks * 2) + b_hi;
            #pragma unroll
            for (int ntp = 0; ntp < 2; ntp++) {
                uint32_t bh[4], bl[4];
                const uint32_t brt = (uint32_t)(wn * 32 + ntp * 16 + b_off) * 128u;
                ldm4(bh, Bb + 0 * MATB + brt + (ub ^ band) * 16);
                ldm4(bl, Bb + 1 * MATB + brt + (ub ^ band) * 16);
                #pragma unroll
                for (int mt = 0; mt < 2; mt++) {
                    mma16816(acc[mt][ntp * 2    ], ah[mt], bh);
                    mma16816(acc[mt][ntp * 2 + 1], ah[mt], bh + 2);
                }
                #pragma unroll
                for (int mt = 0; mt < 2; mt++) {
                    mma16816(acc[mt][ntp * 2    ], ah[mt], bl);
                    mma16816(acc[mt][ntp * 2 + 1], ah[mt], bl + 2);
                }
                #pragma unroll
                for (int mt = 0; mt < 2; mt++) {
                    mma16816(acc[mt][ntp * 2    ], al[mt], bh);
                    mma16816(acc[mt][ntp * 2 + 1], al[mt], bh + 2);
                }
            }
        }
    }

    // ---- epilogue ----
    float* pC = Cf ? (Cf + (size_t)blockIdx.z * sC) : (float*)0;
    __nv_bfloat16* pCh = Chi ? (Chi + (size_t)blockIdx.z * sC) : (__nv_bfloat16*)0;
    __nv_bfloat16* pCl = Clo ? (Clo + (size_t)blockIdx.z * sC) : (__nv_bfloat16*)0;

    #pragma unroll
    for (int mt = 0; mt < 2; mt++) {
        const int row0 = m0 + wm * 32 + mt * 16 + (lane >> 2);
        #pragma unroll
        for (int nt = 0; nt < 4; nt++) {
            const int col = n0 + wn * 32 + nt * 8 + (lane & 3) * 2;
            #pragma unroll
            for (int half = 0; half < 2; half++) {
                const int row = row0 + half * 8;
                float v0 = acc[mt][nt][half * 2    ] * alpha;
                float v1 = acc[mt][nt][half * 2 + 1] * alpha;
                if (bias_mode == 1) {
                    float2 bv = *(const float2*)(bias + col);
                    v0 += bv.x; v1 += bv.y;
                } else if (bias_mode == 2) {
                    float bm = bias[row];
                    v0 += bm; v1 += bm;
                }
                if (mask && col < mask_n) {
                    float2 mv = *(const float2*)(mask + (size_t)row * mask_ld + col);
                    v0 += mv.x; v1 += mv.y;
                }
                if (pC) {
                    float2 ov; ov.x = v0; ov.y = v1;
                    *(float2*)(pC + (size_t)row * ldC + col) = ov;
                } else {
                    __nv_bfloat16 h0, l0, h1, l1;
                    bsplit(v0, h0, l0);
                    bsplit(v1, h1, l1);
                    union { __nv_bfloat16 bb[2]; uint32_t u; } H, L;
                    H.bb[0] = h0; H.bb[1] = h1;
                    L.bb[0] = l0; L.bb[1] = l1;
                    *(uint32_t*)(pCh + (size_t)row * ldC + col) = H.u;
                    *(uint32_t*)(pCl + (size_t)row * ldC + col) = L.u;
                }
            }
        }
    }
}

// ---------------- softmax ----------------
__device__ __forceinline__ float wmax(float v) {
    #pragma unroll
    for (int o = 16; o > 0; o >>= 1) v = fmaxf(v, __shfl_xor_sync(0xFFFFFFFFu, v, o));
    return v;
}
__device__ __forceinline__ float wsum(float v) {
    #pragma unroll
    for (int o = 16; o > 0; o >>= 1) v += __shfl_xor_sync(0xFFFFFFFFu, v, o);
    return v;
}

__global__ void __launch_bounds__(256)
softmax_split(const float* __restrict__ SC, __nv_bfloat16* __restrict__ Phi,
              __nv_bfloat16* __restrict__ Plo)
{
    const size_t base = (size_t)blockIdx.x * TP;
    const float* rrow = SC + base;
    const int tid = threadIdx.x, lane = tid & 31, warp = tid >> 5;
    __shared__ float red[8];

    float v[5];
    float mx = -1e30f;
    #pragma unroll
    for (int i = 0; i < 5; i++) {
        int t = tid + i * 256;
        if (t < TT) { float x = rrow[t]; v[i] = x; mx = fmaxf(mx, x); }
        else v[i] = -1e30f;
    }
    mx = wmax(mx);
    if (lane == 0) red[warp] = mx;
    __syncthreads();
    if (warp == 0) {
        float x = (lane < 8) ? red[lane] : -1e30f;
        x = wmax(x);
        if (lane == 0) red[0] = x;
    }
    __syncthreads();
    mx = red[0];
    __syncthreads();

    float sum = 0.0f;
    #pragma unroll
    for (int i = 0; i < 5; i++) {
        int t = tid + i * 256;
        if (t < TT) { float e = expf(v[i] - mx); v[i] = e; sum += e; }
    }
    sum = wsum(sum);
    if (lane == 0) red[warp] = sum;
    __syncthreads();
    if (warp == 0) {
        float x = (lane < 8) ? red[lane] : 0.0f;
        x = wsum(x);
        if (lane == 0) red[0] = x;
    }
    __syncthreads();
    const float inv = 1.0f / red[0];

    #pragma unroll
    for (int i = 0; i < 5; i++) {
        int t = tid + i * 256;
        if (t < TT) {
            float p = v[i] * inv;
            __nv_bfloat16 hh, ll;
            bsplit(p, hh, ll);
            Phi[base + t] = hh;
            Plo[base + t] = ll;
        } else if (t < TP) {
            Phi[base + t] = __float2bfloat16(0.0f);
            Plo[base + t] = __float2bfloat16(0.0f);
        }
    }
}

// ---------------- launch ----------------
extern "C" void kernel_launch(void* const* d_in, const int* in_sizes, int n_in,
                              void* d_out, int out_size)
{
    const float* x    = (const float*)d_in[0];
    const float* mask = (const float*)d_in[1];
    const float* mem  = (const float*)d_in[2];
    const float* wq   = (const float*)d_in[3];
    const float* bq   = (const float*)d_in[4];
    const float* wk   = (const float*)d_in[5];
    const float* bk   = (const float*)d_in[6];
    const float* wv   = (const float*)d_in[7];
    const float* bv   = (const float*)d_in[8];
    const float* wo   = (const float*)d_in[9];
    const float* bo   = (const float*)d_in[10];
    float* out = (float*)d_out;

    __nv_bfloat16 *kvhi, *kvlo, *qhi, *qlo, *khi, *klo, *vthi, *vtlo, *phi, *plo, *hhi, *hlo;
    __nv_bfloat16 (*whi)[(size_t)DD * DD];
    __nv_bfloat16 (*wlo)[(size_t)DD * DD];
    float* sc;
    cudaGetSymbolAddress((void**)&kvhi, g_kvhi);
    cudaGetSymbolAddress((void**)&kvlo, g_kvlo);
    cudaGetSymbolAddress((void**)&qhi,  g_qhi);
    cudaGetSymbolAddress((void**)&qlo,  g_qlo);
    cudaGetSymbolAddress((void**)&khi,  g_khi);
    cudaGetSymbolAddress((void**)&klo,  g_klo);
    cudaGetSymbolAddress((void**)&vthi, g_vthi);
    cudaGetSymbolAddress((void**)&vtlo, g_vtlo);
    cudaGetSymbolAddress((void**)&sc,   g_sc);
    cudaGetSymbolAddress((void**)&phi,  g_phi);
    cudaGetSymbolAddress((void**)&plo,  g_plo);
    cudaGetSymbolAddress((void**)&hhi,  g_hhi);
    cudaGetSymbolAddress((void**)&hlo,  g_hlo);
    cudaGetSymbolAddress((void**)&whi,  g_whi);
    cudaGetSymbolAddress((void**)&wlo,  g_wlo);

    cudaFuncSetAttribute(gemm3, cudaFuncAttributeMaxDynamicSharedMemorySize, GSMEM);

    // 0: concat + split kv input
    {
        int n4 = NKV * (DD / 4);
        build_kv<<<(n4 + 255) / 256, 256>>>((const float4*)x, (const float4*)mem);
    }
    // 1: split all weights
    {
        int tot = 4 * (DD * DD / 4);
        split_all<<<(tot + 255) / 256, 256>>>((const float4*)wq, (const float4*)wk,
                                              (const float4*)wv, (const float4*)wo);
    }

    // 2: Q = x * wq^T + bq  (batched; A rows skip memory tokens)
    gemm3<<<dim3(DD / 128, SS / 128, BB), 512, GSMEM>>>(
        kvhi, kvlo, (long long)TT * DD, DD, SS,
        whi[0], wlo[0], 0, DD, DD,
        DD, 1.0f, bq, 1, nullptr, 0, 0,
        nullptr, qhi, qlo, (long long)SS * DD, DD);

    // 3: K = kv * wk^T + bk
    gemm3<<<dim3(DD / 128, NKV / 128, 1), 512, GSMEM>>>(
        kvhi, kvlo, 0, DD, NKV,
        whi[1], wlo[1], 0, DD, DD,
        DD, 1.0f, bk, 1, nullptr, 0, 0,
        nullptr, khi, klo, 0, DD);

    // 4: Vt[b] = wv * kv[b]^T + bv(rows)   [768 x TP]
    gemm3<<<dim3(TP / 128, DD / 128, BB), 512, GSMEM>>>(
        whi[2], wlo[2], 0, DD, DD,
        kvhi, kvlo, (long long)TT * DD, DD, TT,
        DD, 1.0f, bv, 2, nullptr, 0, 0,
        nullptr, vthi, vtlo, (long long)DD * TP, TP);

    // 5: scores[b] = SCALE * Q[b] K[b]^T + mask -> fp32
    gemm3<<<dim3(TP / 128, SS / 128, BB), 512, GSMEM>>>(
        qhi, qlo, (long long)SS * DD, DD, SS,
        khi, klo, (long long)TT * DD, DD, TT,
        DD, SCALE, nullptr, 0, mask, TT, TT,
        sc, nullptr, nullptr, (long long)SS * TP, TP);

    // 6: softmax -> split P (pad cols zeroed)
    softmax_split<<<NQ, 256>>>(sc, phi, plo);

    // 7: H[b] = P[b] * Vt[b]^T   (K = 1088, pads are exact zeros)
    gemm3<<<dim3(DD / 128, SS / 128, BB), 512, GSMEM>>>(
        phi, plo, (long long)SS * TP, TP, SS,
        vthi, vtlo, (long long)DD * TP, TP, DD,
        KPV, 1.0f, nullptr, 0, nullptr, 0, 0,
        nullptr, hhi, hlo, (long long)SS * DD, DD);

    // 8: out = H * wo^T + bo -> fp32 d_out
    gemm3<<<dim3(DD / 128, NQ / 128, 1), 512, GSMEM>>>(
        hhi, hlo, 0, DD, NQ,
        whi[3], wlo[3], 0, DD, DD,
        DD, 1.0f, bo, 1, nullptr, 0, 0,
        out, nullptr, nullptr, 0, DD);
}

// round 16
// speedup vs baseline: 1.9575x; 1.0521x over previous
#include <cuda_runtime.h>
#include <cuda_bf16.h>
#include <cstdint>
#include <cstddef>

// ---------------- problem constants ----------------
#define DD   768
#define MTOK 16
#define SS   1024
#define BB   16
#define TT   (SS + MTOK)   // 1040
#define TP   1152          // padded kv len (array stride)
#define KPV  1088          // K extent for P*Vt GEMM (17 x 64)
#define NQ   (BB * SS)     // 16384
#define NKV  (BB * TT)     // 16640
#define SCALE 0.036084391824351615f

// ---------------- scratch (device globals) ----------------
__device__ __align__(256) __nv_bfloat16 g_kvhi[(size_t)NKV * DD];
__device__ __align__(256) __nv_bfloat16 g_kvlo[(size_t)NKV * DD];
__device__ __align__(256) __nv_bfloat16 g_qhi [(size_t)NQ  * DD];
__device__ __align__(256) __nv_bfloat16 g_qlo [(size_t)NQ  * DD];
__device__ __align__(256) __nv_bfloat16 g_khi [(size_t)NKV * DD];
__device__ __align__(256) __nv_bfloat16 g_klo [(size_t)NKV * DD];
__device__ __align__(256) __nv_bfloat16 g_vthi[(size_t)BB * DD * TP];
__device__ __align__(256) __nv_bfloat16 g_vtlo[(size_t)BB * DD * TP];
__device__ __align__(256) float         g_sc  [(size_t)BB * SS * TP];
__device__ __align__(256) __nv_bfloat16 g_phi [(size_t)BB * SS * TP];
__device__ __align__(256) __nv_bfloat16 g_plo [(size_t)BB * SS * TP];
__device__ __align__(256) __nv_bfloat16 g_hhi [(size_t)NQ  * DD];
__device__ __align__(256) __nv_bfloat16 g_hlo [(size_t)NQ  * DD];
__device__ __align__(256) __nv_bfloat16 g_whi [4][(size_t)DD * DD];
__device__ __align__(256) __nv_bfloat16 g_wlo [4][(size_t)DD * DD];

// ---------------- helpers ----------------
__device__ __forceinline__ void bsplit(float f, __nv_bfloat16& h, __nv_bfloat16& l) {
    h = __float2bfloat16(f);
    l = __float2bfloat16(f - __bfloat162float(h));
}
__device__ __forceinline__ uint32_t smem_u32(const void* p) {
    uint32_t a;
    asm("{ .reg .u64 t; cvta.to.shared.u64 t, %1; cvt.u32.u64 %0, t; }" : "=r"(a) : "l"(p));
    return a;
}
__device__ __forceinline__ void cp16(uint32_t dst, const void* src) {
    asm volatile("cp.async.cg.shared.global [%0], [%1], 16;" :: "r"(dst), "l"(src));
}
__device__ __forceinline__ void cp_commit() {
    asm volatile("cp.async.commit_group;" ::: "memory");
}
template <int N>
__device__ __forceinline__ void cp_wait() {
    asm volatile("cp.async.wait_group %0;" :: "n"(N) : "memory");
}
__device__ __forceinline__ void ldm4(uint32_t* r, uint32_t addr) {
    asm volatile("ldmatrix.sync.aligned.m8n8.x4.shared.b16 {%0,%1,%2,%3},[%4];"
                 : "=r"(r[0]), "=r"(r[1]), "=r"(r[2]), "=r"(r[3]) : "r"(addr));
}
__device__ __forceinline__ void mma16816(float* c, const uint32_t* a, const uint32_t* b) {
    asm volatile("mma.sync.aligned.m16n8k16.row.col.f32.bf16.bf16.f32 "
                 "{%0,%1,%2,%3},{%4,%5,%6,%7},{%8,%9},{%0,%1,%2,%3};"
                 : "+f"(c[0]), "+f"(c[1]), "+f"(c[2]), "+f"(c[3])
                 : "r"(a[0]), "r"(a[1]), "r"(a[2]), "r"(a[3]), "r"(b[0]), "r"(b[1]));
}

// ---------------- elementwise prep ----------------
__global__ void build_kv(const float4* __restrict__ x, const float4* __restrict__ mem) {
    const int n4 = NKV * (DD / 4);
    int i = blockIdx.x * 256 + threadIdx.x;
    if (i >= n4) return;
    int d4  = i % (DD / 4);
    int row = i / (DD / 4);
    int b = row / TT, t = row % TT;
    float4 v = (t < SS) ? x[(size_t)(b * SS + t) * (DD / 4) + d4]
                        : mem[(size_t)(t - SS) * (DD / 4) + d4];
    union { __nv_bfloat16 bb[4]; uint2 u; } H, L;
    bsplit(v.x, H.bb[0], L.bb[0]);
    bsplit(v.y, H.bb[1], L.bb[1]);
    bsplit(v.z, H.bb[2], L.bb[2]);
    bsplit(v.w, H.bb[3], L.bb[3]);
    ((uint2*)g_kvhi)[i] = H.u;
    ((uint2*)g_kvlo)[i] = L.u;
}

__global__ void split_all(const float4* __restrict__ w0, const float4* __restrict__ w1,
                          const float4* __restrict__ w2, const float4* __restrict__ w3) {
    const int w4 = DD * DD / 4;
    int i = blockIdx.x * 256 + threadIdx.x;
    if (i >= 4 * w4) return;
    int wsel = i / w4;
    int j    = i % w4;
    const float4* src = (wsel == 0) ? w0 : (wsel == 1) ? w1 : (wsel == 2) ? w2 : w3;
    float4 v = src[j];
    union { __nv_bfloat16 bb[4]; uint2 u; } H, L;
    bsplit(v.x, H.bb[0], L.bb[0]);
    bsplit(v.y, H.bb[1], L.bb[1]);
    bsplit(v.z, H.bb[2], L.bb[2]);
    bsplit(v.w, H.bb[3], L.bb[3]);
    ((uint2*)g_whi[wsel])[j] = H.u;
    ((uint2*)g_wlo[wsel])[j] = L.u;
}

// ---------------- GEMM parameter pack ----------------
struct GP {
    const __nv_bfloat16 *Ahi, *Alo, *Bhi, *Blo;
    long long sA, sB, sC;
    int ldA, mrealA, ldB, nrealB, K;
    float alpha;
    const float* bias; int bias_mode;       // 0 none, 1 over N, 2 over M
    const float* mask; int mask_ld, mask_n;
    float* Cf; __nv_bfloat16 *Chi, *Clo; int ldC;
    int gx, gy;                              // grid decode dims (fused launch)
};

// ---------------- HMMA split-bf16 GEMM body (R11 config) ----------------
// Block 128x128, BK=64, 512 threads, 16 warps (4x4), warp tile 32x32.
// 4 matrices/stage: Ahi|Alo|Bhi|Blo, each 128 x 128B, XOR-8 swizzle. 3-stage.

#define MATB  16384
#define STAGE (4 * MATB)           // 65536
#define GSMEM (3 * STAGE)          // 196608

__device__ __forceinline__ void gemm_body(const GP g, int bxi, int byi, int bzi)
{
    extern __shared__ char smem[];
    const uint32_t sb = smem_u32(smem);
    const int tid  = threadIdx.x;
    const int lane = tid & 31;
    const int warp = tid >> 5;
    const int wm = warp >> 2;
    const int wn = warp & 3;

    const int m0 = byi * 128, n0 = bxi * 128;
    const __nv_bfloat16* pAh = g.Ahi + (size_t)bzi * g.sA;
    const __nv_bfloat16* pAl = g.Alo + (size_t)bzi * g.sA;
    const __nv_bfloat16* pBh = g.Bhi + (size_t)bzi * g.sB;
    const __nv_bfloat16* pBl = g.Blo + (size_t)bzi * g.sB;

    const int r = tid >> 2, q = tid & 3;
    int garow = m0 + r; if (garow >= g.mrealA) garow = g.mrealA - 1;
    int gbrow = n0 + r; if (gbrow >= g.nrealB) gbrow = g.nrealB - 1;
    const __nv_bfloat16* srcAh = pAh + (size_t)garow * g.ldA + q * 16;
    const __nv_bfloat16* srcAl = pAl + (size_t)garow * g.ldA + q * 16;
    const __nv_bfloat16* srcBh = pBh + (size_t)gbrow * g.ldB + q * 16;
    const __nv_bfloat16* srcBl = pBl + (size_t)gbrow * g.ldB + q * 16;
    uint32_t dstu[2];
    #pragma unroll
    for (int j = 0; j < 2; j++)
        dstu[j] = (uint32_t)r * 128u + (uint32_t)((((q << 1) + j) ^ (r & 7)) * 16);

    const int nchunk = g.K >> 6;

    auto prefetch = [&](int c, int stg) {
        const uint32_t so = sb + (uint32_t)stg * STAGE;
        const int k0 = c << 6;
        #pragma unroll
        for (int j = 0; j < 2; j++) cp16(so + 0 * MATB + dstu[j], srcAh + k0 + j * 8);
        #pragma unroll
        for (int j = 0; j < 2; j++) cp16(so + 1 * MATB + dstu[j], srcAl + k0 + j * 8);
        #pragma unroll
        for (int j = 0; j < 2; j++) cp16(so + 2 * MATB + dstu[j], srcBh + k0 + j * 8);
        #pragma unroll
        for (int j = 0; j < 2; j++) cp16(so + 3 * MATB + dstu[j], srcBl + k0 + j * 8);
    };

    float acc[2][4][4];
    #pragma unroll
    for (int i = 0; i < 2; i++)
        #pragma unroll
        for (int j = 0; j < 4; j++)
            #pragma unroll
            for (int p = 0; p < 4; p++) acc[i][j][p] = 0.0f;

    const uint32_t band = (uint32_t)(lane & 7);
    const uint32_t a_hi = (uint32_t)(lane >> 4);
    uint32_t arowt[2];
    #pragma unroll
    for (int mt = 0; mt < 2; mt++)
        arowt[mt] = (uint32_t)(wm * 32 + mt * 16 + (lane & 15)) * 128u;
    const uint32_t b_off = (uint32_t)(((lane >> 4) & 1) * 8 + (lane & 7));
    const uint32_t b_hi  = (uint32_t)((lane >> 3) & 1);

    prefetch(0, 0); cp_commit();
    if (nchunk > 1) prefetch(1, 1);
    cp_commit();

    for (int c = 0; c < nchunk; c++) {
        cp_wait<1>();
        __syncthreads();
        if (c + 2 < nchunk) prefetch(c + 2, (c + 2) % 3);
        cp_commit();

        const uint32_t Ab = sb + (uint32_t)(c % 3) * STAGE;
        const uint32_t Bb = Ab + 2 * MATB;

        #pragma unroll
        for (int ks = 0; ks < 4; ks++) {
            uint32_t ah[2][4], al[2][4];
            const uint32_t ua = (uint32_t)(ks * 2) + a_hi;
            #pragma unroll
            for (int mt = 0; mt < 2; mt++) {
                ldm4(ah[mt], Ab + 0 * MATB + arowt[mt] + (ua ^ band) * 16);
                ldm4(al[mt], Ab + 1 * MATB + arowt[mt] + (ua ^ band) * 16);
            }
            const uint32_t ub = (uint32_t)(ks * 2) + b_hi;
            #pragma unroll
            for (int ntp = 0; ntp < 2; ntp++) {
                uint32_t bh[4], bl[4];
                const uint32_t brt = (uint32_t)(wn * 32 + ntp * 16 + b_off) * 128u;
                ldm4(bh, Bb + 0 * MATB + brt + (ub ^ band) * 16);
                ldm4(bl, Bb + 1 * MATB + brt + (ub ^ band) * 16);
                #pragma unroll
                for (int mt = 0; mt < 2; mt++) {
                    mma16816(acc[mt][ntp * 2    ], ah[mt], bh);
                    mma16816(acc[mt][ntp * 2 + 1], ah[mt], bh + 2);
                }
                #pragma unroll
                for (int mt = 0; mt < 2; mt++) {
                    mma16816(acc[mt][ntp * 2    ], ah[mt], bl);
                    mma16816(acc[mt][ntp * 2 + 1], ah[mt], bl + 2);
                }
                #pragma unroll
                for (int mt = 0; mt < 2; mt++) {
                    mma16816(acc[mt][ntp * 2    ], al[mt], bh);
                    mma16816(acc[mt][ntp * 2 + 1], al[mt], bh + 2);
                }
            }
        }
    }

    // ---- epilogue ----
    float* pC = g.Cf ? (g.Cf + (size_t)bzi * g.sC) : (float*)0;
    __nv_bfloat16* pCh = g.Chi ? (g.Chi + (size_t)bzi * g.sC) : (__nv_bfloat16*)0;
    __nv_bfloat16* pCl = g.Clo ? (g.Clo + (size_t)bzi * g.sC) : (__nv_bfloat16*)0;

    #pragma unroll
    for (int mt = 0; mt < 2; mt++) {
        const int row0 = m0 + wm * 32 + mt * 16 + (lane >> 2);
        #pragma unroll
        for (int nt = 0; nt < 4; nt++) {
            const int col = n0 + wn * 32 + nt * 8 + (lane & 3) * 2;
            #pragma unroll
            for (int half = 0; half < 2; half++) {
                const int row = row0 + half * 8;
                float v0 = acc[mt][nt][half * 2    ] * g.alpha;
                float v1 = acc[mt][nt][half * 2 + 1] * g.alpha;
                if (g.bias_mode == 1) {
                    float2 bv = *(const float2*)(g.bias + col);
                    v0 += bv.x; v1 += bv.y;
                } else if (g.bias_mode == 2) {
                    float bm = g.bias[row];
                    v0 += bm; v1 += bm;
                }
                if (g.mask && col < g.mask_n) {
                    float2 mv = *(const float2*)(g.mask + (size_t)row * g.mask_ld + col);
                    v0 += mv.x; v1 += mv.y;
                }
                if (pC) {
                    float2 ov; ov.x = v0; ov.y = v1;
                    *(float2*)(pC + (size_t)row * g.ldC + col) = ov;
                } else {
                    __nv_bfloat16 h0, l0, h1, l1;
                    bsplit(v0, h0, l0);
                    bsplit(v1, h1, l1);
                    union { __nv_bfloat16 bb[2]; uint32_t u; } H, L;
                    H.bb[0] = h0; H.bb[1] = h1;
                    L.bb[0] = l0; L.bb[1] = l1;
                    *(uint32_t*)(pCh + (size_t)row * g.ldC + col) = H.u;
                    *(uint32_t*)(pCl + (size_t)row * g.ldC + col) = L.u;
                }
            }
        }
    }
}

__global__ void __launch_bounds__(512, 1)
gemm3(GP g)
{
    gemm_body(g, blockIdx.x, blockIdx.y, blockIdx.z);
}

// fused projections: one grid covering Q, K, Vt GEMMs (kills two launch tails)
__global__ void __launch_bounds__(512, 1)
proj_fused(GP p0, GP p1, GP p2, int c0, int c1)
{
    int lb = blockIdx.x;
    GP g;
    int idx;
    if (lb < c0)            { g = p0; idx = lb; }
    else if (lb < c0 + c1)  { g = p1; idx = lb - c0; }
    else                    { g = p2; idx = lb - c0 - c1; }
    int bx = idx % g.gx;
    int t  = idx / g.gx;
    int by = t % g.gy;
    int bz = t / g.gy;
    gemm_body(g, bx, by, bz);
}

// ---------------- softmax ----------------
__device__ __forceinline__ float wmax(float v) {
    #pragma unroll
    for (int o = 16; o > 0; o >>= 1) v = fmaxf(v, __shfl_xor_sync(0xFFFFFFFFu, v, o));
    return v;
}
__device__ __forceinline__ float wsum(float v) {
    #pragma unroll
    for (int o = 16; o > 0; o >>= 1) v += __shfl_xor_sync(0xFFFFFFFFu, v, o);
    return v;
}

__global__ void __launch_bounds__(256)
softmax_split(const float* __restrict__ SC, __nv_bfloat16* __restrict__ Phi,
              __nv_bfloat16* __restrict__ Plo)
{
    const size_t base = (size_t)blockIdx.x * TP;
    const float* rrow = SC + base;
    const int tid = threadIdx.x, lane = tid & 31, warp = tid >> 5;
    __shared__ float red[8];

    float v[5];
    float mx = -1e30f;
    #pragma unroll
    for (int i = 0; i < 5; i++) {
        int t = tid + i * 256;
        if (t < TT) { float x = rrow[t]; v[i] = x; mx = fmaxf(mx, x); }
        else v[i] = -1e30f;
    }
    mx = wmax(mx);
    if (lane == 0) red[warp] = mx;
    __syncthreads();
    if (warp == 0) {
        float x = (lane < 8) ? red[lane] : -1e30f;
        x = wmax(x);
        if (lane == 0) red[0] = x;
    }
    __syncthreads();
    mx = red[0];
    __syncthreads();

    float sum = 0.0f;
    #pragma unroll
    for (int i = 0; i < 5; i++) {
        int t = tid + i * 256;
        if (t < TT) { float e = expf(v[i] - mx); v[i] = e; sum += e; }
    }
    sum = wsum(sum);
    if (lane == 0) red[warp] = sum;
    __syncthreads();
    if (warp == 0) {
        float x = (lane < 8) ? red[lane] : 0.0f;
        x = wsum(x);
        if (lane == 0) red[0] = x;
    }
    __syncthreads();
    const float inv = 1.0f / red[0];

    #pragma unroll
    for (int i = 0; i < 5; i++) {
        int t = tid + i * 256;
        if (t < TT) {
            float p = v[i] * inv;
            __nv_bfloat16 hh, ll;
            bsplit(p, hh, ll);
            Phi[base + t] = hh;
            Plo[base + t] = ll;
        } else if (t < TP) {
            Phi[base + t] = __float2bfloat16(0.0f);
            Plo[base + t] = __float2bfloat16(0.0f);
        }
    }
}

// ---------------- launch ----------------
extern "C" void kernel_launch(void* const* d_in, const int* in_sizes, int n_in,
                              void* d_out, int out_size)
{
    const float* x    = (const float*)d_in[0];
    const float* mask = (const float*)d_in[1];
    const float* mem  = (const float*)d_in[2];
    const float* wq   = (const float*)d_in[3];
    const float* bq   = (const float*)d_in[4];
    const float* wk   = (const float*)d_in[5];
    const float* bk   = (const float*)d_in[6];
    const float* wv   = (const float*)d_in[7];
    const float* bv   = (const float*)d_in[8];
    const float* wo   = (const float*)d_in[9];
    const float* bo   = (const float*)d_in[10];
    float* out = (float*)d_out;

    __nv_bfloat16 *kvhi, *kvlo, *qhi, *qlo, *khi, *klo, *vthi, *vtlo, *phi, *plo, *hhi, *hlo;
    __nv_bfloat16 (*whi)[(size_t)DD * DD];
    __nv_bfloat16 (*wlo)[(size_t)DD * DD];
    float* sc;
    cudaGetSymbolAddress((void**)&kvhi, g_kvhi);
    cudaGetSymbolAddress((void**)&kvlo, g_kvlo);
    cudaGetSymbolAddress((void**)&qhi,  g_qhi);
    cudaGetSymbolAddress((void**)&qlo,  g_qlo);
    cudaGetSymbolAddress((void**)&khi,  g_khi);
    cudaGetSymbolAddress((void**)&klo,  g_klo);
    cudaGetSymbolAddress((void**)&vthi, g_vthi);
    cudaGetSymbolAddress((void**)&vtlo, g_vtlo);
    cudaGetSymbolAddress((void**)&sc,   g_sc);
    cudaGetSymbolAddress((void**)&phi,  g_phi);
    cudaGetSymbolAddress((void**)&plo,  g_plo);
    cudaGetSymbolAddress((void**)&hhi,  g_hhi);
    cudaGetSymbolAddress((void**)&hlo,  g_hlo);
    cudaGetSymbolAddress((void**)&whi,  g_whi);
    cudaGetSymbolAddress((void**)&wlo,  g_wlo);

    cudaFuncSetAttribute(gemm3,      cudaFuncAttributeMaxDynamicSharedMemorySize, GSMEM);
    cudaFuncSetAttribute(proj_fused, cudaFuncAttributeMaxDynamicSharedMemorySize, GSMEM);

    // 0: concat + split kv input
    {
        int n4 = NKV * (DD / 4);
        build_kv<<<(n4 + 255) / 256, 256>>>((const float4*)x, (const float4*)mem);
    }
    // 1: split all weights
    {
        int tot = 4 * (DD * DD / 4);
        split_all<<<(tot + 255) / 256, 256>>>((const float4*)wq, (const float4*)wk,
                                              (const float4*)wv, (const float4*)wo);
    }

    // 2: fused Q/K/Vt projections (one launch, one tail)
    GP pq{}, pk{}, pv{};
    // Q = x * wq^T + bq  (batched so A rows skip memory tokens)
    pq.Ahi = kvhi; pq.Alo = kvlo; pq.sA = (long long)TT * DD; pq.ldA = DD; pq.mrealA = SS;
    pq.Bhi = whi[0]; pq.Blo = wlo[0]; pq.sB = 0; pq.ldB = DD; pq.nrealB = DD;
    pq.K = DD; pq.alpha = 1.0f; pq.bias = bq; pq.bias_mode = 1;
    pq.mask = nullptr; pq.mask_ld = 0; pq.mask_n = 0;
    pq.Cf = nullptr; pq.Chi = qhi; pq.Clo = qlo; pq.sC = (long long)SS * DD; pq.ldC = DD;
    pq.gx = DD / 128; pq.gy = SS / 128;                 // gz = BB
    // K = kv * wk^T + bk
    pk.Ahi = kvhi; pk.Alo = kvlo; pk.sA = 0; pk.ldA = DD; pk.mrealA = NKV;
    pk.Bhi = whi[1]; pk.Blo = wlo[1]; pk.sB = 0; pk.ldB = DD; pk.nrealB = DD;
    pk.K = DD; pk.alpha = 1.0f; pk.bias = bk; pk.bias_mode = 1;
    pk.mask = nullptr; pk.mask_ld = 0; pk.mask_n = 0;
    pk.Cf = nullptr; pk.Chi = khi; pk.Clo = klo; pk.sC = 0; pk.ldC = DD;
    pk.gx = DD / 128; pk.gy = NKV / 128;                // gz = 1
    // Vt[b] = wv * kv[b]^T + bv(rows)
    pv.Ahi = whi[2]; pv.Alo = wlo[2]; pv.sA = 0; pv.ldA = DD; pv.mrealA = DD;
    pv.Bhi = kvhi; pv.Blo = kvlo; pv.sB = (long long)TT * DD; pv.ldB = DD; pv.nrealB = TT;
    pv.K = DD; pv.alpha = 1.0f; pv.bias = bv; pv.bias_mode = 2;
    pv.mask = nullptr; pv.mask_ld = 0; pv.mask_n = 0;
    pv.Cf = nullptr; pv.Chi = vthi; pv.Clo = vtlo; pv.sC = (long long)DD * TP; pv.ldC = TP;
    pv.gx = TP / 128; pv.gy = DD / 128;                 // gz = BB
    const int cq = pq.gx * pq.gy * BB;                  // 768
    const int ck = pk.gx * pk.gy * 1;                   // 780
    const int cv = pv.gx * pv.gy * BB;                  // 864
    proj_fused<<<cq + ck + cv, 512, GSMEM>>>(pq, pk, pv, cq, ck);

    // 3: scores[b] = SCALE * Q[b] K[b]^T + mask -> fp32
    {
        GP s{};
        s.Ahi = qhi; s.Alo = qlo; s.sA = (long long)SS * DD; s.ldA = DD; s.mrealA = SS;
        s.Bhi = khi; s.Blo = klo; s.sB = (long long)TT * DD; s.ldB = DD; s.nrealB = TT;
        s.K = DD; s.alpha = SCALE; s.bias = nullptr; s.bias_mode = 0;
        s.mask = mask; s.mask_ld = TT; s.mask_n = TT;
        s.Cf = sc; s.Chi = nullptr; s.Clo = nullptr; s.sC = (long long)SS * TP; s.ldC = TP;
        s.gx = TP / 128; s.gy = SS / 128;
        gemm3<<<dim3(TP / 128, SS / 128, BB), 512, GSMEM>>>(s);
    }

    // 4: softmax -> split P (pad cols zeroed)
    softmax_split<<<NQ, 256>>>(sc, phi, plo);

    // 5: H[b] = P[b] * Vt[b]^T   (K = 1088, pads are exact zeros)
    {
        GP h{};
        h.Ahi = phi; h.Alo = plo; h.sA = (long long)SS * TP; h.ldA = TP; h.mrealA = SS;
        h.Bhi = vthi; h.Blo = vtlo; h.sB = (long long)DD * TP; h.ldB = TP; h.nrealB = DD;
        h.K = KPV; h.alpha = 1.0f; h.bias = nullptr; h.bias_mode = 0;
        h.mask = nullptr; h.mask_ld = 0; h.mask_n = 0;
        h.Cf = nullptr; h.Chi = hhi; h.Clo = hlo; h.sC = (long long)SS * DD; h.ldC = DD;
        h.gx = DD / 128; h.gy = SS / 128;
        gemm3<<<dim3(DD / 128, SS / 128, BB), 512, GSMEM>>>(h);
    }

    // 6: out = H * wo^T + bo -> fp32 d_out
    {
        GP o{};
        o.Ahi = hhi; o.Alo = hlo; o.sA = 0; o.ldA = DD; o.mrealA = NQ;
        o.Bhi = whi[3]; o.Blo = wlo[3]; o.sB = 0; o.ldB = DD; o.nrealB = DD;
        o.K = DD; o.alpha = 1.0f; o.bias = bo; o.bias_mode = 1;
        o.mask = nullptr; o.mask_ld = 0; o.mask_n = 0;
        o.Cf = out; o.Chi = nullptr; o.Clo = nullptr; o.sC = 0; o.ldC = DD;
        o.gx = DD / 128; o.gy = NQ / 128;
        gemm3<<<dim3(DD / 128, NQ / 128, 1), 512, GSMEM>>>(o);
    }
}

// round 17
// speedup vs baseline: 2.1574x; 1.1021x over previous
#include <cuda_runtime.h>
#include <cuda_bf16.h>
#include <cstdint>
#include <cstddef>

// ---------------- problem constants ----------------
#define DD   768
#define MTOK 16
#define SS   1024
#define BB   16
#define TT   (SS + MTOK)   // 1040
#define TP   1152          // padded kv len (array stride)
#define KPV  1088          // K extent for P*Vt GEMM (17 x 64)
#define NQ   (BB * SS)     // 16384
#define NKV  (BB * TT)     // 16640
#define SCALE 0.036084391824351615f

// ---------------- scratch (device globals) ----------------
__device__ __align__(256) __nv_bfloat16 g_kvhi[(size_t)NKV * DD];
__device__ __align__(256) __nv_bfloat16 g_kvlo[(size_t)NKV * DD];
__device__ __align__(256) __nv_bfloat16 g_qhi [(size_t)NQ  * DD];
__device__ __align__(256) __nv_bfloat16 g_qlo [(size_t)NQ  * DD];
__device__ __align__(256) __nv_bfloat16 g_khi [(size_t)NKV * DD];
__device__ __align__(256) __nv_bfloat16 g_klo [(size_t)NKV * DD];
__device__ __align__(256) __nv_bfloat16 g_vthi[(size_t)BB * DD * TP];
__device__ __align__(256) __nv_bfloat16 g_vtlo[(size_t)BB * DD * TP];
__device__ __align__(256) float         g_sc  [(size_t)BB * SS * TP];
__device__ __align__(256) __nv_bfloat16 g_phi [(size_t)BB * SS * TP];
__device__ __align__(256) __nv_bfloat16 g_plo [(size_t)BB * SS * TP];
__device__ __align__(256) __nv_bfloat16 g_hhi [(size_t)NQ  * DD];
__device__ __align__(256) __nv_bfloat16 g_hlo [(size_t)NQ  * DD];
__device__ __align__(256) __nv_bfloat16 g_whi [4][(size_t)DD * DD];
__device__ __align__(256) __nv_bfloat16 g_wlo [4][(size_t)DD * DD];

// ---------------- helpers ----------------
__device__ __forceinline__ void bsplit(float f, __nv_bfloat16& h, __nv_bfloat16& l) {
    h = __float2bfloat16(f);
    l = __float2bfloat16(f - __bfloat162float(h));
}
__device__ __forceinline__ uint32_t smem_u32(const void* p) {
    uint32_t a;
    asm("{ .reg .u64 t; cvta.to.shared.u64 t, %1; cvt.u32.u64 %0, t; }" : "=r"(a) : "l"(p));
    return a;
}
__device__ __forceinline__ void cp16(uint32_t dst, const void* src) {
    asm volatile("cp.async.cg.shared.global [%0], [%1], 16;" :: "r"(dst), "l"(src));
}
__device__ __forceinline__ void cp_commit() {
    asm volatile("cp.async.commit_group;" ::: "memory");
}
template <int N>
__device__ __forceinline__ void cp_wait() {
    asm volatile("cp.async.wait_group %0;" :: "n"(N) : "memory");
}
__device__ __forceinline__ void ldm4(uint32_t* r, uint32_t addr) {
    asm volatile("ldmatrix.sync.aligned.m8n8.x4.shared.b16 {%0,%1,%2,%3},[%4];"
                 : "=r"(r[0]), "=r"(r[1]), "=r"(r[2]), "=r"(r[3]) : "r"(addr));
}
__device__ __forceinline__ void mma16816(float* c, const uint32_t* a, const uint32_t* b) {
    asm volatile("mma.sync.aligned.m16n8k16.row.col.f32.bf16.bf16.f32 "
                 "{%0,%1,%2,%3},{%4,%5,%6,%7},{%8,%9},{%0,%1,%2,%3};"
                 : "+f"(c[0]), "+f"(c[1]), "+f"(c[2]), "+f"(c[3])
                 : "r"(a[0]), "r"(a[1]), "r"(a[2]), "r"(a[3]), "r"(b[0]), "r"(b[1]));
}

// ---------------- merged elementwise prep (kv concat/split + weight split) ----------------
__global__ void prep_all(const float4* __restrict__ x, const float4* __restrict__ mem,
                         const float4* __restrict__ w0, const float4* __restrict__ w1,
                         const float4* __restrict__ w2, const float4* __restrict__ w3)
{
    const int nkv4 = NKV * (DD / 4);
    const int w4   = DD * DD / 4;
    int i = blockIdx.x * 256 + threadIdx.x;
    if (i < nkv4) {
        int d4  = i % (DD / 4);
        int row = i / (DD / 4);
        int b = row / TT, t = row % TT;
        float4 v = (t < SS) ? x[(size_t)(b * SS + t) * (DD / 4) + d4]
                            : mem[(size_t)(t - SS) * (DD / 4) + d4];
        union { __nv_bfloat16 bb[4]; uint2 u; } H, L;
        bsplit(v.x, H.bb[0], L.bb[0]);
        bsplit(v.y, H.bb[1], L.bb[1]);
        bsplit(v.z, H.bb[2], L.bb[2]);
        bsplit(v.w, H.bb[3], L.bb[3]);
        ((uint2*)g_kvhi)[i] = H.u;
        ((uint2*)g_kvlo)[i] = L.u;
        return;
    }
    i -= nkv4;
    if (i >= 4 * w4) return;
    int wsel = i / w4;
    int j    = i % w4;
    const float4* src = (wsel == 0) ? w0 : (wsel == 1) ? w1 : (wsel == 2) ? w2 : w3;
    float4 v = src[j];
    union { __nv_bfloat16 bb[4]; uint2 u; } H, L;
    bsplit(v.x, H.bb[0], L.bb[0]);
    bsplit(v.y, H.bb[1], L.bb[1]);
    bsplit(v.z, H.bb[2], L.bb[2]);
    bsplit(v.w, H.bb[3], L.bb[3]);
    ((uint2*)g_whi[wsel])[j] = H.u;
    ((uint2*)g_wlo[wsel])[j] = L.u;
}

// ---------------- GEMM parameter pack ----------------
struct GP {
    const __nv_bfloat16 *Ahi, *Alo, *Bhi, *Blo;
    long long sA, sB, sC;
    int ldA, mrealA, ldB, nrealB, K;
    float alpha;
    const float* bias; int bias_mode;       // 0 none, 1 over N, 2 over M
    const float* mask; int mask_ld, mask_n;
    float* Cf; __nv_bfloat16 *Chi, *Clo; int ldC;
    int gx, gy;
};

// ---------------- HMMA split-bf16 GEMM body ----------------
// Block 128x128, BK=64, 512 threads, 16 warps (4x4), warp tile 32x32.
// 4 matrices/stage (Ahi|Alo|Bhi|Blo), 128 x 128B rows, XOR-8 swizzle, 3-stage.
// cp.async for chunk c+2 is SPREAD across the 4 ks steps (no post-barrier burst).

#define MATB  16384
#define STAGE (4 * MATB)           // 65536
#define GSMEM (3 * STAGE)          // 196608

__device__ __forceinline__ void gemm_body(const GP g, int bxi, int byi, int bzi)
{
    extern __shared__ char smem[];
    const uint32_t sb = smem_u32(smem);
    const int tid  = threadIdx.x;
    const int lane = tid & 31;
    const int warp = tid >> 5;
    const int wm = warp >> 2;
    const int wn = warp & 3;

    const int m0 = byi * 128, n0 = bxi * 128;
    const __nv_bfloat16* pAh = g.Ahi + (size_t)bzi * g.sA;
    const __nv_bfloat16* pAl = g.Alo + (size_t)bzi * g.sA;
    const __nv_bfloat16* pBh = g.Bhi + (size_t)bzi * g.sB;
    const __nv_bfloat16* pBl = g.Blo + (size_t)bzi * g.sB;

    const int r = tid >> 2, q = tid & 3;
    int garow = m0 + r; if (garow >= g.mrealA) garow = g.mrealA - 1;
    int gbrow = n0 + r; if (gbrow >= g.nrealB) gbrow = g.nrealB - 1;
    const __nv_bfloat16* srcAh = pAh + (size_t)garow * g.ldA + q * 16;
    const __nv_bfloat16* srcAl = pAl + (size_t)garow * g.ldA + q * 16;
    const __nv_bfloat16* srcBh = pBh + (size_t)gbrow * g.ldB + q * 16;
    const __nv_bfloat16* srcBl = pBl + (size_t)gbrow * g.ldB + q * 16;
    uint32_t dstu[2];
    #pragma unroll
    for (int j = 0; j < 2; j++)
        dstu[j] = (uint32_t)r * 128u + (uint32_t)((((q << 1) + j) ^ (r & 7)) * 16);

    const int nchunk = g.K >> 6;

    auto prefetch_full = [&](int c, int stg) {
        const uint32_t so = sb + (uint32_t)stg * STAGE;
        const int k0 = c << 6;
        #pragma unroll
        for (int j = 0; j < 2; j++) cp16(so + 0 * MATB + dstu[j], srcAh + k0 + j * 8);
        #pragma unroll
        for (int j = 0; j < 2; j++) cp16(so + 1 * MATB + dstu[j], srcAl + k0 + j * 8);
        #pragma unroll
        for (int j = 0; j < 2; j++) cp16(so + 2 * MATB + dstu[j], srcBh + k0 + j * 8);
        #pragma unroll
        for (int j = 0; j < 2; j++) cp16(so + 3 * MATB + dstu[j], srcBl + k0 + j * 8);
    };

    float acc[2][4][4];
    #pragma unroll
    for (int i = 0; i < 2; i++)
        #pragma unroll
        for (int j = 0; j < 4; j++)
            #pragma unroll
            for (int p = 0; p < 4; p++) acc[i][j][p] = 0.0f;

    const uint32_t band = (uint32_t)(lane & 7);
    const uint32_t a_hi = (uint32_t)(lane >> 4);
    uint32_t arowt[2];
    #pragma unroll
    for (int mt = 0; mt < 2; mt++)
        arowt[mt] = (uint32_t)(wm * 32 + mt * 16 + (lane & 15)) * 128u;
    const uint32_t b_off = (uint32_t)(((lane >> 4) & 1) * 8 + (lane & 7));
    const uint32_t b_hi  = (uint32_t)((lane >> 3) & 1);

    prefetch_full(0, 0); cp_commit();
    if (nchunk > 1) prefetch_full(1, 1);
    cp_commit();

    for (int c = 0; c < nchunk; c++) {
        cp_wait<1>();
        __syncthreads();

        const uint32_t Ab = sb + (uint32_t)(c % 3) * STAGE;
        const uint32_t Bb = Ab + 2 * MATB;

        const bool pf = (c + 2 < nchunk);
        const uint32_t pso = sb + (uint32_t)((c + 2) % 3) * STAGE;
        const int pk0 = (c + 2) << 6;

        #pragma unroll
        for (int ks = 0; ks < 4; ks++) {
            // spread prefetch of chunk c+2: one matrix per ks step
            if (pf) {
                const uint32_t mo = pso + (uint32_t)ks * MATB;
                const __nv_bfloat16* s =
                    (ks == 0) ? srcAh : (ks == 1) ? srcAl : (ks == 2) ? srcBh : srcBl;
                cp16(mo + dstu[0], s + pk0);
                cp16(mo + dstu[1], s + pk0 + 8);
            }
            uint32_t ah[2][4], al[2][4];
            const uint32_t ua = (uint32_t)(ks * 2) + a_hi;
            #pragma unroll
            for (int mt = 0; mt < 2; mt++) {
                ldm4(ah[mt], Ab + 0 * MATB + arowt[mt] + (ua ^ band) * 16);
                ldm4(al[mt], Ab + 1 * MATB + arowt[mt] + (ua ^ band) * 16);
            }
            const uint32_t ub = (uint32_t)(ks * 2) + b_hi;
            #pragma unroll
            for (int ntp = 0; ntp < 2; ntp++) {
                uint32_t bh[4], bl[4];
                const uint32_t brt = (uint32_t)(wn * 32 + ntp * 16 + b_off) * 128u;
                ldm4(bh, Bb + 0 * MATB + brt + (ub ^ band) * 16);
                ldm4(bl, Bb + 1 * MATB + brt + (ub ^ band) * 16);
                #pragma unroll
                for (int mt = 0; mt < 2; mt++) {
                    mma16816(acc[mt][ntp * 2    ], ah[mt], bh);
                    mma16816(acc[mt][ntp * 2 + 1], ah[mt], bh + 2);
                }
                #pragma unroll
                for (int mt = 0; mt < 2; mt++) {
                    mma16816(acc[mt][ntp * 2    ], ah[mt], bl);
                    mma16816(acc[mt][ntp * 2 + 1], ah[mt], bl + 2);
                }
                #pragma unroll
                for (int mt = 0; mt < 2; mt++) {
                    mma16816(acc[mt][ntp * 2    ], al[mt], bh);
                    mma16816(acc[mt][ntp * 2 + 1], al[mt], bh + 2);
                }
            }
        }
        cp_commit();    // close group for chunk c+2 (empty group when !pf — harmless)
    }

    // ---- epilogue ----
    float* pC = g.Cf ? (g.Cf + (size_t)bzi * g.sC) : (float*)0;
    __nv_bfloat16* pCh = g.Chi ? (g.Chi + (size_t)bzi * g.sC) : (__nv_bfloat16*)0;
    __nv_bfloat16* pCl = g.Clo ? (g.Clo + (size_t)bzi * g.sC) : (__nv_bfloat16*)0;

    #pragma unroll
    for (int mt = 0; mt < 2; mt++) {
        const int row0 = m0 + wm * 32 + mt * 16 + (lane >> 2);
        #pragma unroll
        for (int nt = 0; nt < 4; nt++) {
            const int col = n0 + wn * 32 + nt * 8 + (lane & 3) * 2;
            #pragma unroll
            for (int half = 0; half < 2; half++) {
                const int row = row0 + half * 8;
                float v0 = acc[mt][nt][half * 2    ] * g.alpha;
                float v1 = acc[mt][nt][half * 2 + 1] * g.alpha;
                if (g.bias_mode == 1) {
                    float2 bv = *(const float2*)(g.bias + col);
                    v0 += bv.x; v1 += bv.y;
                } else if (g.bias_mode == 2) {
                    float bm = g.bias[row];
                    v0 += bm; v1 += bm;
                }
                if (g.mask && col < g.mask_n) {
                    float2 mv = *(const float2*)(g.mask + (size_t)row * g.mask_ld + col);
                    v0 += mv.x; v1 += mv.y;
                }
                if (pC) {
                    float2 ov; ov.x = v0; ov.y = v1;
                    *(float2*)(pC + (size_t)row * g.ldC + col) = ov;
                } else {
                    __nv_bfloat16 h0, l0, h1, l1;
                    bsplit(v0, h0, l0);
                    bsplit(v1, h1, l1);
                    union { __nv_bfloat16 bb[2]; uint32_t u; } H, L;
                    H.bb[0] = h0; H.bb[1] = h1;
                    L.bb[0] = l0; L.bb[1] = l1;
                    *(uint32_t*)(pCh + (size_t)row * g.ldC + col) = H.u;
                    *(uint32_t*)(pCl + (size_t)row * g.ldC + col) = L.u;
                }
            }
        }
    }
}

__global__ void __launch_bounds__(512, 1)
gemm3(GP g)
{
    gemm_body(g, blockIdx.x, blockIdx.y, blockIdx.z);
}

__global__ void __launch_bounds__(512, 1)
proj_fused(GP p0, GP p1, GP p2, int c0, int c1)
{
    int lb = blockIdx.x;
    GP g;
    int idx;
    if (lb < c0)            { g = p0; idx = lb; }
    else if (lb < c0 + c1)  { g = p1; idx = lb - c0; }
    else                    { g = p2; idx = lb - c0 - c1; }
    int bx = idx % g.gx;
    int t  = idx / g.gx;
    int by = t % g.gy;
    int bz = t / g.gy;
    gemm_body(g, bx, by, bz);
}

// ---------------- softmax ----------------
__device__ __forceinline__ float wmax(float v) {
    #pragma unroll
    for (int o = 16; o > 0; o >>= 1) v = fmaxf(v, __shfl_xor_sync(0xFFFFFFFFu, v, o));
    return v;
}
__device__ __forceinline__ float wsum(float v) {
    #pragma unroll
    for (int o = 16; o > 0; o >>= 1) v += __shfl_xor_sync(0xFFFFFFFFu, v, o);
    return v;
}

__global__ void __launch_bounds__(256)
softmax_split(const float* __restrict__ SC, __nv_bfloat16* __restrict__ Phi,
              __nv_bfloat16* __restrict__ Plo)
{
    const size_t base = (size_t)blockIdx.x * TP;
    const float* rrow = SC + base;
    const int tid = threadIdx.x, lane = tid & 31, warp = tid >> 5;
    __shared__ float red[8];

    float v[5];
    float mx = -1e30f;
    #pragma unroll
    for (int i = 0; i < 5; i++) {
        int t = tid + i * 256;
        if (t < TT) { float x = rrow[t]; v[i] = x; mx = fmaxf(mx, x); }
        else v[i] = -1e30f;
    }
    mx = wmax(mx);
    if (lane == 0) red[warp] = mx;
    __syncthreads();
    if (warp == 0) {
        float x = (lane < 8) ? red[lane] : -1e30f;
        x = wmax(x);
        if (lane == 0) red[0] = x;
    }
    __syncthreads();
    mx = red[0];
    __syncthreads();

    float sum = 0.0f;
    #pragma unroll
    for (int i = 0; i < 5; i++) {
        int t = tid + i * 256;
        if (t < TT) { float e = expf(v[i] - mx); v[i] = e; sum += e; }
    }
    sum = wsum(sum);
    if (lane == 0) red[warp] = sum;
    __syncthreads();
    if (warp == 0) {
        float x = (lane < 8) ? red[lane] : 0.0f;
        x = wsum(x);
        if (lane == 0) red[0] = x;
    }
    __syncthreads();
    const float inv = 1.0f / red[0];

    #pragma unroll
    for (int i = 0; i < 5; i++) {
        int t = tid + i * 256;
        if (t < TT) {
            float p = v[i] * inv;
            __nv_bfloat16 hh, ll;
            bsplit(p, hh, ll);
            Phi[base + t] = hh;
            Plo[base + t] = ll;
        } else if (t < TP) {
            Phi[base + t] = __float2bfloat16(0.0f);
            Plo[base + t] = __float2bfloat16(0.0f);
        }
    }
}

// ---------------- launch ----------------
extern "C" void kernel_launch(void* const* d_in, const int* in_sizes, int n_in,
                              void* d_out, int out_size)
{
    const float* x    = (const float*)d_in[0];
    const float* mask = (const float*)d_in[1];
    const float* mem  = (const float*)d_in[2];
    const float* wq   = (const float*)d_in[3];
    const float* bq   = (const float*)d_in[4];
    const float* wk   = (const float*)d_in[5];
    const float* bk   = (const float*)d_in[6];
    const float* wv   = (const float*)d_in[7];
    const float* bv   = (const float*)d_in[8];
    const float* wo   = (const float*)d_in[9];
    const float* bo   = (const float*)d_in[10];
    float* out = (float*)d_out;

    __nv_bfloat16 *kvhi, *kvlo, *qhi, *qlo, *khi, *klo, *vthi, *vtlo, *phi, *plo, *hhi, *hlo;
    __nv_bfloat16 (*whi)[(size_t)DD * DD];
    __nv_bfloat16 (*wlo)[(size_t)DD * DD];
    float* sc;
    cudaGetSymbolAddress((void**)&kvhi, g_kvhi);
    cudaGetSymbolAddress((void**)&kvlo, g_kvlo);
    cudaGetSymbolAddress((void**)&qhi,  g_qhi);
    cudaGetSymbolAddress((void**)&qlo,  g_qlo);
    cudaGetSymbolAddress((void**)&khi,  g_khi);
    cudaGetSymbolAddress((void**)&klo,  g_klo);
    cudaGetSymbolAddress((void**)&vthi, g_vthi);
    cudaGetSymbolAddress((void**)&vtlo, g_vtlo);
    cudaGetSymbolAddress((void**)&sc,   g_sc);
    cudaGetSymbolAddress((void**)&phi,  g_phi);
    cudaGetSymbolAddress((void**)&plo,  g_plo);
    cudaGetSymbolAddress((void**)&hhi,  g_hhi);
    cudaGetSymbolAddress((void**)&hlo,  g_hlo);
    cudaGetSymbolAddress((void**)&whi,  g_whi);
    cudaGetSymbolAddress((void**)&wlo,  g_wlo);

    cudaFuncSetAttribute(gemm3,      cudaFuncAttributeMaxDynamicSharedMemorySize, GSMEM);
    cudaFuncSetAttribute(proj_fused, cudaFuncAttributeMaxDynamicSharedMemorySize, GSMEM);

    // 0: merged prep (kv concat/split + weight split), one launch
    {
        int tot = NKV * (DD / 4) + 4 * (DD * DD / 4);
        prep_all<<<(tot + 255) / 256, 256>>>((const float4*)x, (const float4*)mem,
                                             (const float4*)wq, (const float4*)wk,
                                             (const float4*)wv, (const float4*)wo);
    }

    // 1: fused Q/K/Vt projections
    GP pq{}, pk{}, pv{};
    pq.Ahi = kvhi; pq.Alo = kvlo; pq.sA = (long long)TT * DD; pq.ldA = DD; pq.mrealA = SS;
    pq.Bhi = whi[0]; pq.Blo = wlo[0]; pq.sB = 0; pq.ldB = DD; pq.nrealB = DD;
    pq.K = DD; pq.alpha = 1.0f; pq.bias = bq; pq.bias_mode = 1;
    pq.mask = nullptr; pq.mask_ld = 0; pq.mask_n = 0;
    pq.Cf = nullptr; pq.Chi = qhi; pq.Clo = qlo; pq.sC = (long long)SS * DD; pq.ldC = DD;
    pq.gx = DD / 128; pq.gy = SS / 128;
    pk.Ahi = kvhi; pk.Alo = kvlo; pk.sA = 0; pk.ldA = DD; pk.mrealA = NKV;
    pk.Bhi = whi[1]; pk.Blo = wlo[1]; pk.sB = 0; pk.ldB = DD; pk.nrealB = DD;
    pk.K = DD; pk.alpha = 1.0f; pk.bias = bk; pk.bias_mode = 1;
    pk.mask = nullptr; pk.mask_ld = 0; pk.mask_n = 0;
    pk.Cf = nullptr; pk.Chi = khi; pk.Clo = klo; pk.sC = 0; pk.ldC = DD;
    pk.gx = DD / 128; pk.gy = NKV / 128;
    pv.Ahi = whi[2]; pv.Alo = wlo[2]; pv.sA = 0; pv.ldA = DD; pv.mrealA = DD;
    pv.Bhi = kvhi; pv.Blo = kvlo; pv.sB = (long long)TT * DD; pv.ldB = DD; pv.nrealB = TT;
    pv.K = DD; pv.alpha = 1.0f; pv.bias = bv; pv.bias_mode = 2;
    pv.mask = nullptr; pv.mask_ld = 0; pv.mask_n = 0;
    pv.Cf = nullptr; pv.Chi = vthi; pv.Clo = vtlo; pv.sC = (long long)DD * TP; pv.ldC = TP;
    pv.gx = TP / 128; pv.gy = DD / 128;
    const int cq = pq.gx * pq.gy * BB;
    const int ck = pk.gx * pk.gy * 1;
    const int cv = pv.gx * pv.gy * BB;
    proj_fused<<<cq + ck + cv, 512, GSMEM>>>(pq, pk, pv, cq, ck);

    // 2: scores
    {
        GP s{};
        s.Ahi = qhi; s.Alo = qlo; s.sA = (long long)SS * DD; s.ldA = DD; s.mrealA = SS;
        s.Bhi = khi; s.Blo = klo; s.sB = (long long)TT * DD; s.ldB = DD; s.nrealB = TT;
        s.K = DD; s.alpha = SCALE; s.bias = nullptr; s.bias_mode = 0;
        s.mask = mask; s.mask_ld = TT; s.mask_n = TT;
        s.Cf = sc; s.Chi = nullptr; s.Clo = nullptr; s.sC = (long long)SS * TP; s.ldC = TP;
        s.gx = TP / 128; s.gy = SS / 128;
        gemm3<<<dim3(TP / 128, SS / 128, BB), 512, GSMEM>>>(s);
    }

    // 3: softmax -> split P
    softmax_split<<<NQ, 256>>>(sc, phi, plo);

    // 4: H = P * Vt^T
    {
        GP h{};
        h.Ahi = phi; h.Alo = plo; h.sA = (long long)SS * TP; h.ldA = TP; h.mrealA = SS;
        h.Bhi = vthi; h.Blo = vtlo; h.sB = (long long)DD * TP; h.ldB = TP; h.nrealB = DD;
        h.K = KPV; h.alpha = 1.0f; h.bias = nullptr; h.bias_mode = 0;
        h.mask = nullptr; h.mask_ld = 0; h.mask_n = 0;
        h.Cf = nullptr; h.Chi = hhi; h.Clo = hlo; h.sC = (long long)SS * DD; h.ldC = DD;
        h.gx = DD / 128; h.gy = SS / 128;
        gemm3<<<dim3(DD / 128, SS / 128, BB), 512, GSMEM>>>(h);
    }

    // 5: out = H * wo^T + bo
    {
        GP o{};
        o.Ahi = hhi; o.Alo = hlo; o.sA = 0; o.ldA = DD; o.mrealA = NQ;
        o.Bhi = whi[3]; o.Blo = wlo[3]; o.sB = 0; o.ldB = DD; o.nrealB = DD;
        o.K = DD; o.alpha = 1.0f; o.bias = bo; o.bias_mode = 1;
        o.mask = nullptr; o.mask_ld = 0; o.mask_n = 0;
        o.Cf = out; o.Chi = nullptr; o.Clo = nullptr; o.sC = 0; o.ldC = DD;
        o.gx = DD / 128; o.gy = NQ / 128;
        gemm3<<<dim3(DD / 128, NQ / 128, 1), 512, GSMEM>>>(o);
    }
}